// round 4
// baseline (speedup 1.0000x reference)
#include <cuda_runtime.h>
#include <cuda_bf16.h>
#include <cstdint>
#include <math.h>

// ================= problem constants =================
#define BQ   4096
#define DD   2048
#define PROJ 2730
#define UPN  5460
#define N_ELE (BQ*DD)

// split-bf16 K layouts: K' = 3*Kpad, segments [A_hi | A_lo | A_hi] x [B_hi | B_hi | B_lo]
#define KP1   2048            // gates / up
#define LDA1  (3*KP1)         // 6144
#define KP2   2752            // down (2730 padded to mult of 64)
#define LDA2  (3*KP2)         // 8256
#define NPAD_UP 5632          // 22 * 256

// ================= scratch (static device globals) =================
__device__ __align__(256) __nv_bfloat16 gA [(size_t)BQ*LDA2];        // activation split (max layout)
__device__ __align__(256) __nv_bfloat16 gBg[(size_t)4*DD*LDA1];      // W_i,f,z,o transposed+split
__device__ __align__(256) __nv_bfloat16 gBu[(size_t)NPAD_UP*LDA1];   // up_w
__device__ __align__(256) __nv_bfloat16 gBd[(size_t)DD*LDA2];        // down_w
__device__ __align__(16) float g_xt[N_ELE];
__device__ __align__(16) float g_gates[(size_t)4*N_ELE];             // gate preacts; reused for `up`
__device__ __align__(16) float g_ht[N_ELE];
__device__ __align__(16) float g_gated[(size_t)BQ*PROJ];

// ================= PTX helpers =================
__device__ __forceinline__ uint32_t smem_u32(const void* p){
    uint32_t a; asm("{ .reg .u64 t; cvta.to.shared.u64 t, %1; cvt.u32.u64 %0, t; }" : "=r"(a) : "l"(p));
    return a;
}
#define CP16(s, g) asm volatile("cp.async.cg.shared.global [%0], [%1], 16;" :: "r"(s), "l"(g) : "memory")
#define CP_COMMIT() asm volatile("cp.async.commit_group;" ::: "memory")

#define LDSM_X4(r0,r1,r2,r3,addr) \
    asm volatile("ldmatrix.sync.aligned.m8n8.x4.shared.b16 {%0,%1,%2,%3}, [%4];" \
        : "=r"(r0), "=r"(r1), "=r"(r2), "=r"(r3) : "r"(addr))
#define MMA16816(d, a0,a1,a2,a3, b0,b1) \
    asm volatile("mma.sync.aligned.m16n8k16.row.col.f32.bf16.bf16.f32 " \
        "{%0,%1,%2,%3}, {%4,%5,%6,%7}, {%8,%9}, {%0,%1,%2,%3};" \
        : "+f"((d)[0]), "+f"((d)[1]), "+f"((d)[2]), "+f"((d)[3]) \
        : "r"(a0), "r"(a1), "r"(a2), "r"(a3), "r"(b0), "r"(b1))

// ================= HMMA GEMM: C[M,N] = A[M,K'] * Bt[N,K']^T =================
// A [M,K'] bf16 row-major (lda elems); Bt [Npad,K'] bf16 row-major (ldb elems)
// CTA tile 128x256x64, 8 warps (2m x 4n), warp tile 64x64.
// SMEM rows are 128B (8 granules of 16B), SW128 swizzle: granule' = g ^ (row&7)
#define BM 128
#define BN 256
#define BK 64
#define SB_OFF   16384u
#define STAGE    49152u
#define SMEMSZ   98304

__global__ void __launch_bounds__(256, 1) mma_gemm(
    const __nv_bfloat16* __restrict__ A, long lda,
    const __nv_bfloat16* __restrict__ B, long ldb,
    float* __restrict__ C, int N, int ldc, int Kp,
    long bStride, long cStride,
    const float* __restrict__ bias,
    const float* __restrict__ resid)
{
    extern __shared__ __align__(1024) char smem[];
    uint32_t base = smem_u32(smem);

    int tid  = threadIdx.x;
    int lane = tid & 31;
    int wid  = tid >> 5;
    int n0 = blockIdx.x * BN;
    int m0 = blockIdx.y * BM;
    B += (long)blockIdx.z * bStride;
    C += (long)blockIdx.z * cStride;

    // ---- loader slots
    // A: 128 rows x 8 granules; thread -> row tid>>1, granules (tid&1)*4 .. +3
    int lrA = tid >> 1;
    int gA0 = (tid & 1) * 4;
    const char* gAp = (const char*)(A + (long)(m0 + lrA) * lda) + gA0*16;
    uint32_t aswz[4];
#pragma unroll
    for (int q = 0; q < 4; q++)
        aswz[q] = (uint32_t)((lrA*8 + ((gA0 + q) ^ (lrA & 7))) * 16);
    // B: 256 rows x 8 granules; thread -> row tid, granules 0..7
    const char* gBp = (const char*)(B + (long)(n0 + tid) * ldb);
    uint32_t bswz[8];
#pragma unroll
    for (int q = 0; q < 8; q++)
        bswz[q] = (uint32_t)((tid*8 + (q ^ (tid & 7))) * 16) + SB_OFF;

    // ---- warp tiling: 2(m) x 4(n), warp tile 64x64
    int warp_m = wid & 1;
    int warp_n = wid >> 1;

    // ldmatrix row bases
    int rAq[4];
#pragma unroll
    for (int mt = 0; mt < 4; mt++) rAq[mt] = warp_m*64 + mt*16 + (lane & 15);
    int cAoff = lane >> 4;                 // 0/1 (k-granule half)
    int rBq[4];
#pragma unroll
    for (int np = 0; np < 4; np++) rBq[np] = warp_n*64 + np*16 + ((lane >> 4) << 3) + (lane & 7);
    int cBoff = (lane >> 3) & 1;           // 0/1

    float acc[4][8][4];
#pragma unroll
    for (int mt = 0; mt < 4; mt++)
#pragma unroll
        for (int nt = 0; nt < 8; nt++)
#pragma unroll
            for (int q = 0; q < 4; q++) acc[mt][nt][q] = 0.f;

    int NC = Kp / BK;

    // prologue: chunk 0 -> stage 0
    {
#pragma unroll
        for (int q = 0; q < 4; q++) CP16(base + aswz[q], gAp + q*16);
#pragma unroll
        for (int q = 0; q < 8; q++) CP16(base + bswz[q], gBp + q*16);
        CP_COMMIT();
    }

    for (int c = 0; c < NC; c++) {
        if (c + 1 < NC) {
            uint32_t sb = ((c + 1) & 1) ? STAGE : 0u;
            long ko = (long)(c + 1) * 128;    // 64 bf16 = 128B per row per chunk
#pragma unroll
            for (int q = 0; q < 4; q++) CP16(base + sb + aswz[q], gAp + ko + q*16);
#pragma unroll
            for (int q = 0; q < 8; q++) CP16(base + sb + bswz[q], gBp + ko + q*16);
            CP_COMMIT();
            asm volatile("cp.async.wait_group 1;" ::: "memory");
        } else {
            asm volatile("cp.async.wait_group 0;" ::: "memory");
        }
        __syncthreads();

        uint32_t sA = base + ((c & 1) ? STAGE : 0u);
        uint32_t sB = sA + SB_OFF;

#pragma unroll
        for (int kk = 0; kk < 4; kk++) {
            uint32_t a[4][4], b[8][2];
            int cA = kk*2 + cAoff;
#pragma unroll
            for (int mt = 0; mt < 4; mt++) {
                int r = rAq[mt];
                uint32_t ad = sA + (uint32_t)((r*8 + (cA ^ (r & 7))) * 16);
                LDSM_X4(a[mt][0], a[mt][1], a[mt][2], a[mt][3], ad);
            }
            int cB = kk*2 + cBoff;
#pragma unroll
            for (int np = 0; np < 4; np++) {
                int r = rBq[np];
                uint32_t bd = sB + (uint32_t)((r*8 + (cB ^ (r & 7))) * 16);
                LDSM_X4(b[2*np][0], b[2*np][1], b[2*np+1][0], b[2*np+1][1], bd);
            }
#pragma unroll
            for (int mt = 0; mt < 4; mt++)
#pragma unroll
                for (int nt = 0; nt < 8; nt++)
                    MMA16816(acc[mt][nt], a[mt][0], a[mt][1], a[mt][2], a[mt][3],
                             b[nt][0], b[nt][1]);
        }
        __syncthreads();
    }

    // ---- epilogue
#pragma unroll
    for (int mt = 0; mt < 4; mt++) {
        int r0 = m0 + warp_m*64 + mt*16 + (lane >> 2);
        int r1 = r0 + 8;
        size_t o0 = (size_t)r0 * ldc;
        size_t o1 = (size_t)r1 * ldc;
#pragma unroll
        for (int nt = 0; nt < 8; nt++) {
            int col = n0 + warp_n*64 + nt*8 + (lane & 3)*2;
            if (col >= N) continue;
            float v0 = acc[mt][nt][0], v1 = acc[mt][nt][1];
            float v2 = acc[mt][nt][2], v3 = acc[mt][nt][3];
            if (bias)  { float b0 = bias[col], b1 = bias[col+1];
                         v0 += b0; v1 += b1; v2 += b0; v3 += b1; }
            if (resid) { const float2 q0 = *(const float2*)(resid + o0 + col);
                         const float2 q1 = *(const float2*)(resid + o1 + col);
                         v0 += q0.x; v1 += q0.y; v2 += q1.x; v3 += q1.y; }
            *(float2*)(C + o0 + col) = make_float2(v0, v1);
            *(float2*)(C + o1 + col) = make_float2(v2, v3);
        }
    }
}

// ================= split conversions =================
// A split: dst row = [hi(0..Kpad) | lo | hi], zero-padded where k >= K
__global__ void convA_k(const float* __restrict__ src, int K, int Kpad, long ldd,
                        __nv_bfloat16* __restrict__ dst)
{
    long idx = (long)blockIdx.x * blockDim.x + threadIdx.x;
    long tot = (long)BQ * Kpad;
    if (idx >= tot) return;
    int m = (int)(idx / Kpad), k = (int)(idx % Kpad);
    float v = (k < K) ? src[(long)m * K + k] : 0.f;
    __nv_bfloat16 hi = __float2bfloat16(v);
    __nv_bfloat16 lo = __float2bfloat16(v - __bfloat162float(hi));
    __nv_bfloat16* row = dst + (long)m * ldd;
    row[k] = hi; row[Kpad + k] = lo; row[2*Kpad + k] = hi;
}

// W[K,N] -> Bt[Npad, 3*Kpad]: row n = [hi | hi | lo], transposed, zero-padded
__global__ void convW_k(const float* __restrict__ W, int K, int N, int Kpad, int Npad,
                        long ldd, __nv_bfloat16* __restrict__ dst)
{
    __shared__ float t[32][33];
    int k0 = blockIdx.x * 32, nn0 = blockIdx.y * 32;
    int tx = threadIdx.x, ty = threadIdx.y;   // (32, 8)
#pragma unroll
    for (int i = ty; i < 32; i += 8) {
        int k = k0 + i, n = nn0 + tx;
        t[i][tx] = (k < K && n < N) ? W[(long)k * N + n] : 0.f;
    }
    __syncthreads();
#pragma unroll
    for (int i = ty; i < 32; i += 8) {
        int n = nn0 + i;
        if (n >= Npad) continue;
        int k = k0 + tx;
        float v = t[tx][i];
        __nv_bfloat16 hi = __float2bfloat16(v);
        __nv_bfloat16 lo = __float2bfloat16(v - __bfloat162float(hi));
        __nv_bfloat16* row = dst + (long)n * ldd;
        row[k] = hi; row[Kpad + k] = hi; row[2*Kpad + k] = lo;
    }
}

// ================= LayerNorm (eps = 2048) =================
__global__ void ln_kernel(const float* __restrict__ seq,
                          const float* __restrict__ sc,
                          const float* __restrict__ bi)
{
    int b = blockIdx.x, t = threadIdx.x;
    const float* row = seq + ((size_t)b << 11);
    float v[8]; float s = 0.f, sq = 0.f;
#pragma unroll
    for (int q = 0; q < 8; q++) { v[q] = row[q*256 + t]; s += v[q]; sq = fmaf(v[q], v[q], sq); }
    __shared__ float sh_s[8], sh_q[8];
    __shared__ float s_mu, s_inv;
#pragma unroll
    for (int o = 16; o; o >>= 1) {
        s  += __shfl_down_sync(0xffffffffu, s,  o);
        sq += __shfl_down_sync(0xffffffffu, sq, o);
    }
    int warp = t >> 5, lane = t & 31;
    if (lane == 0) { sh_s[warp] = s; sh_q[warp] = sq; }
    __syncthreads();
    if (t == 0) {
        float ts = 0.f, tq = 0.f;
        for (int w = 0; w < 8; w++) { ts += sh_s[w]; tq += sh_q[w]; }
        float mu = ts / 2048.f;
        float var = tq / 2048.f - mu*mu;
        s_mu = mu; s_inv = rsqrtf(var + 2048.0f);
    }
    __syncthreads();
    float mu = s_mu, inv = s_inv;
#pragma unroll
    for (int q = 0; q < 8; q++) {
        int col = q*256 + t;
        g_xt[((size_t)b << 11) + col] = (v[q] - mu) * inv * sc[col] + bi[col];
    }
}

// ================= gating + block-diag recurrence =================
__global__ void gate_kernel(
    const float* __restrict__ b_i, const float* __restrict__ b_f,
    const float* __restrict__ b_z, const float* __restrict__ b_o,
    const float* __restrict__ Riw, const float* __restrict__ Rib,
    const float* __restrict__ Rfw, const float* __restrict__ Rfb,
    const float* __restrict__ Rzw, const float* __restrict__ Rzb,
    const float* __restrict__ Row_, const float* __restrict__ Rob,
    const float* __restrict__ c_tm1, const float* __restrict__ n_tm1,
    const float* __restrict__ h_tm1, const float* __restrict__ m_tm1,
    float* __restrict__ out, int write_states)
{
    size_t idx = (size_t)blockIdx.x * blockDim.x + threadIdx.x;
    if (idx >= (size_t)N_ELE) return;
    int b = (int)(idx >> 11);
    int j = (int)(idx & 2047);
    int h = j >> 7;
    int rem = j & 127;
    int n = rem >> 3;
    int e = rem & 7;

    const float* hp = h_tm1 + ((size_t)b << 11) + (h << 7) + (n << 3);
    float hv[8];
#pragma unroll
    for (int d = 0; d < 8; d++) hv[d] = hp[d];
    int sb = n*8 + e;
    int wb = n*64 + e;
    float bi_ = Rib[sb], bf_ = Rfb[sb], bz_ = Rzb[sb], bo_ = Rob[sb];
#pragma unroll
    for (int d = 0; d < 8; d++) {
        float hd = hv[d];
        bi_ = fmaf(hd, Riw[wb + d*8], bi_);
        bf_ = fmaf(hd, Rfw[wb + d*8], bf_);
        bz_ = fmaf(hd, Rzw[wb + d*8], bz_);
        bo_ = fmaf(hd, Row_[wb + d*8], bo_);
    }

    float it = g_gates[idx]                    + b_i[j] + bi_;
    float ft = g_gates[(size_t)N_ELE   + idx]  + b_f[j] + bf_;
    float zt = g_gates[(size_t)2*N_ELE + idx]  + b_z[j] + bz_;
    float ot = g_gates[(size_t)3*N_ELE + idx]  + b_o[j] + bo_;

    float mprev = m_tm1[idx];
    float mt = fmaxf(ft + mprev, it);
    float ie = expf(it - mt);
    float fe = expf(ft - mt + mprev);
    float z  = tanhf(zt);
    float ct = fe * c_tm1[idx] + ie * z;
    float nt = fe * n_tm1[idx] + ie;
    float o  = 1.f / (1.f + expf(-ot));
    float ht = o * (ct / nt);

    g_ht[idx] = ht;
    if (write_states) {
        out[(size_t)N_ELE   + idx] = ct;
        out[(size_t)2*N_ELE + idx] = nt;
        out[(size_t)3*N_ELE + idx] = ht;
        out[(size_t)4*N_ELE + idx] = mt;
    }
}

// ================= GroupNorm =================
__global__ void gn_kernel(const float* __restrict__ sc, const float* __restrict__ bi)
{
    int b = blockIdx.x, t = threadIdx.x;
    __shared__ float row[2048];
    __shared__ float ps[256], pq[256];
    __shared__ float gmu[16], gis[16];
    const float* hr = g_ht + ((size_t)b << 11);
#pragma unroll
    for (int q = 0; q < 8; q++) row[q*256 + t] = hr[q*256 + t];
    __syncthreads();

    int g = t >> 4, p = t & 15;
    float s = 0.f, sq = 0.f;
#pragma unroll
    for (int dg = 0; dg < 8; dg++) {
        float v = row[p*128 + g*8 + dg];
        s += v; sq = fmaf(v, v, sq);
    }
    ps[t] = s; pq[t] = sq;
    __syncthreads();
    for (int st = 8; st > 0; st >>= 1) {
        if (p < st) { ps[t] += ps[t + st]; pq[t] += pq[t + st]; }
        __syncthreads();
    }
    if (p == 0) {
        float mu = ps[t] / 128.f;
        float var = pq[t] / 128.f - mu*mu;
        gmu[g] = mu; gis[g] = rsqrtf(var + 1e-6f);
    }
    __syncthreads();
#pragma unroll
    for (int q = 0; q < 8; q++) {
        int col = q*256 + t;
        int hd = col & 127;
        int gg = hd >> 3;
        float v = (row[col] - gmu[gg]) * gis[gg];
        g_xt[((size_t)b << 11) + col] = v * sc[hd] + bi[hd];
    }
}

// ================= GLU =================
__global__ void glu_kernel()
{
    long idx = (long)blockIdx.x * blockDim.x + threadIdx.x;
    long tot = (long)BQ * PROJ;
    if (idx >= tot) return;
    int b = (int)(idx / PROJ);
    int j = (int)(idx % PROJ);
    const float* up = g_gates + (long)b * UPN;
    float a = up[j];
    float x = up[j + PROJ];
    float x3 = x * x * x;
    float gg = 0.5f * x * (1.f + tanhf(0.7978845608028654f * (x + 0.044715f * x3)));
    g_gated[idx] = a + gg;
}

// ================= driver =================
extern "C" void kernel_launch(void* const* d_in, const int* in_sizes, int n_in,
                              void* d_out, int out_size)
{
    const float* seq      = (const float*)d_in[0];
    const float* c_tm1    = (const float*)d_in[1];
    const float* n_tm1    = (const float*)d_in[2];
    const float* h_tm1    = (const float*)d_in[3];
    const float* m_tm1    = (const float*)d_in[4];
    const float* ln_scale = (const float*)d_in[5];
    const float* ln_bias  = (const float*)d_in[6];
    const float* W_z      = (const float*)d_in[7];
    const float* b_z      = (const float*)d_in[8];
    const float* W_i      = (const float*)d_in[9];
    const float* b_i      = (const float*)d_in[10];
    const float* W_f      = (const float*)d_in[11];
    const float* b_f      = (const float*)d_in[12];
    const float* W_o      = (const float*)d_in[13];
    const float* b_o      = (const float*)d_in[14];
    const float* R_z_w    = (const float*)d_in[15];
    const float* R_z_b    = (const float*)d_in[16];
    const float* R_i_w    = (const float*)d_in[17];
    const float* R_i_b    = (const float*)d_in[18];
    const float* R_f_w    = (const float*)d_in[19];
    const float* R_f_b    = (const float*)d_in[20];
    const float* R_o_w    = (const float*)d_in[21];
    const float* R_o_b    = (const float*)d_in[22];
    const float* gn_scale = (const float*)d_in[23];
    const float* gn_bias  = (const float*)d_in[24];
    const float* up_w     = (const float*)d_in[25];
    const float* up_b     = (const float*)d_in[26];
    const float* down_w   = (const float*)d_in[27];
    const float* down_b   = (const float*)d_in[28];
    float* out = (float*)d_out;

    int write_states = (out_size >= 5 * N_ELE) ? 1 : 0;

    cudaFuncSetAttribute(mma_gemm, cudaFuncAttributeMaxDynamicSharedMemorySize, SMEMSZ);

    void *pA, *pBg, *pBu, *pBd, *pXT, *pG, *pGated;
    cudaGetSymbolAddress(&pA,  gA);
    cudaGetSymbolAddress(&pBg, gBg);
    cudaGetSymbolAddress(&pBu, gBu);
    cudaGetSymbolAddress(&pBd, gBd);
    cudaGetSymbolAddress(&pXT, g_xt);
    cudaGetSymbolAddress(&pG,  g_gates);
    cudaGetSymbolAddress(&pGated, g_gated);
    __nv_bfloat16* A  = (__nv_bfloat16*)pA;
    __nv_bfloat16* Bg = (__nv_bfloat16*)pBg;
    __nv_bfloat16* Bu = (__nv_bfloat16*)pBu;
    __nv_bfloat16* Bd = (__nv_bfloat16*)pBd;
    float* xt    = (float*)pXT;
    float* gates = (float*)pG;
    float* gated = (float*)pGated;

    dim3 cw(32, 8);

    // weight conversions (order-independent w.r.t. the activation chain)
    convW_k<<<dim3(KP1/32, DD/32), cw>>>(W_i, DD, DD, KP1, DD, LDA1, Bg + 0L*DD*LDA1);
    convW_k<<<dim3(KP1/32, DD/32), cw>>>(W_f, DD, DD, KP1, DD, LDA1, Bg + 1L*DD*LDA1);
    convW_k<<<dim3(KP1/32, DD/32), cw>>>(W_z, DD, DD, KP1, DD, LDA1, Bg + 2L*DD*LDA1);
    convW_k<<<dim3(KP1/32, DD/32), cw>>>(W_o, DD, DD, KP1, DD, LDA1, Bg + 3L*DD*LDA1);
    convW_k<<<dim3(KP1/32, NPAD_UP/32), cw>>>(up_w,   DD,   UPN, KP1, NPAD_UP, LDA1, Bu);
    convW_k<<<dim3(KP2/32, DD/32), cw>>>(down_w, PROJ, DD,  KP2, DD,      LDA2, Bd);

    // 1. LayerNorm
    ln_kernel<<<BQ, 256>>>(seq, ln_scale, ln_bias);

    // 2. split x_t
    convA_k<<<(unsigned)(((long)BQ*KP1 + 255)/256), 256>>>(xt, DD, KP1, LDA1, A);

    // 3. four gate GEMMs (batched over z): slabs [i,f,z,o]
    mma_gemm<<<dim3(DD/BN, BQ/BM, 4), 256, SMEMSZ>>>(
        A, LDA1, Bg, LDA1, gates, DD, DD, LDA1,
        (long)DD*LDA1, (long)N_ELE, nullptr, nullptr);

    // 4. gating + recurrence + states
    gate_kernel<<<N_ELE/256, 256>>>(b_i, b_f, b_z, b_o,
                                    R_i_w, R_i_b, R_f_w, R_f_b,
                                    R_z_w, R_z_b, R_o_w, R_o_b,
                                    c_tm1, n_tm1, h_tm1, m_tm1,
                                    out, write_states);

    // 5. GroupNorm -> g_xt
    gn_kernel<<<BQ, 256>>>(gn_scale, gn_bias);

    // 6. split GN output, up GEMM (+bias)
    convA_k<<<(unsigned)(((long)BQ*KP1 + 255)/256), 256>>>(xt, DD, KP1, LDA1, A);
    mma_gemm<<<dim3(NPAD_UP/BN, BQ/BM, 1), 256, SMEMSZ>>>(
        A, LDA1, Bu, LDA1, gates, UPN, UPN, LDA1, 0, 0, up_b, nullptr);

    // 7. GLU
    glu_kernel<<<(unsigned)(((long)BQ*PROJ + 255)/256), 256>>>();

    // 8. split gated, down GEMM (+bias +residual)
    convA_k<<<(unsigned)(((long)BQ*KP2 + 255)/256), 256>>>(gated, PROJ, KP2, LDA2, A);
    mma_gemm<<<dim3(DD/BN, BQ/BM, 1), 256, SMEMSZ>>>(
        A, LDA2, Bd, LDA2, out, DD, DD, LDA2, 0, 0, down_b, seq);
}

// round 5
// speedup vs baseline: 1.2098x; 1.2098x over previous
#include <cuda_runtime.h>
#include <cuda_bf16.h>
#include <cstdint>
#include <math.h>

// ================= problem constants =================
#define BQ   4096
#define DD   2048
#define PROJ 2730
#define UPN  5460
#define N_ELE (BQ*DD)

// split-bf16 K layouts: K' = 3*Kpad, segments [A_hi | A_lo | A_hi] x [B_hi | B_hi | B_lo]
#define KP1   2048            // gates / up
#define LDA1  (3*KP1)         // 6144
#define KP2   2752            // down (2730 padded to mult of 64)
#define LDA2  (3*KP2)         // 8256
#define NPAD_UP 5632

// ================= scratch (static device globals) =================
__device__ __align__(256) __nv_bfloat16 gA [(size_t)BQ*LDA2];
__device__ __align__(256) __nv_bfloat16 gBg[(size_t)4*DD*LDA1];
__device__ __align__(256) __nv_bfloat16 gBu[(size_t)NPAD_UP*LDA1];
__device__ __align__(256) __nv_bfloat16 gBd[(size_t)DD*LDA2];
__device__ __align__(16) float g_xt[N_ELE];
__device__ __align__(16) float g_gates[(size_t)4*N_ELE];
__device__ __align__(16) float g_ht[N_ELE];
__device__ __align__(16) float g_gated[(size_t)BQ*PROJ];

// ================= PTX helpers =================
__device__ __forceinline__ uint32_t smem_u32(const void* p){
    uint32_t a; asm("{ .reg .u64 t; cvta.to.shared.u64 t, %1; cvt.u32.u64 %0, t; }" : "=r"(a) : "l"(p));
    return a;
}
#define CP16(s, g) asm volatile("cp.async.cg.shared.global [%0], [%1], 16;" :: "r"(s), "l"(g) : "memory")
#define CP_COMMIT() asm volatile("cp.async.commit_group;" ::: "memory")

#define LDSM_X4(r0,r1,r2,r3,addr) \
    asm volatile("ldmatrix.sync.aligned.m8n8.x4.shared.b16 {%0,%1,%2,%3}, [%4];" \
        : "=r"(r0), "=r"(r1), "=r"(r2), "=r"(r3) : "r"(addr))
#define MMA16816(d, a0,a1,a2,a3, b0,b1) \
    asm volatile("mma.sync.aligned.m16n8k16.row.col.f32.bf16.bf16.f32 " \
        "{%0,%1,%2,%3}, {%4,%5,%6,%7}, {%8,%9}, {%0,%1,%2,%3};" \
        : "+f"((d)[0]), "+f"((d)[1]), "+f"((d)[2]), "+f"((d)[3]) \
        : "r"(a0), "r"(a1), "r"(a2), "r"(a3), "r"(b0), "r"(b1))

// ================= HMMA GEMM: C[M,N] = A[M,K'] * Bt[N,K']^T =================
// CTA tile 128x128x64, 8 warps (2m x 4n), warp tile 64x32, 3-stage cp.async,
// 2 CTAs/SM. SMEM rows 128B (8 x 16B granules), swizzle g' = g ^ (row&7).
#define BM 128
#define BN 128
#define BK 64
#define SB_OFF    16384u
#define STAGE_SZ  32768u
#define SMEMSZ    98304

__global__ void __launch_bounds__(256, 2) mma_gemm(
    const __nv_bfloat16* __restrict__ A, long lda,
    const __nv_bfloat16* __restrict__ B, long ldb,
    float* __restrict__ C, int N, int ldc, int Kp,
    long bStride, long cStride,
    const float* __restrict__ bias,
    const float* __restrict__ resid)
{
    extern __shared__ __align__(1024) char smem[];
    uint32_t base = smem_u32(smem);

    int tid  = threadIdx.x;
    int lane = tid & 31;
    int wid  = tid >> 5;
    int n0 = blockIdx.x * BN;
    int m0 = blockIdx.y * BM;
    B += (long)blockIdx.z * bStride;
    C += (long)blockIdx.z * cStride;

    // ---- loader slots: row = tid>>1 (0..127), 4 granules starting at (tid&1)*4
    int lr  = tid >> 1;
    int g0  = (tid & 1) * 4;
    const char* gAp = (const char*)(A + (long)(m0 + lr) * lda) + g0*16;
    const char* gBp = (const char*)(B + (long)(n0 + lr) * ldb) + g0*16;
    uint32_t aswz[4];
#pragma unroll
    for (int q = 0; q < 4; q++)
        aswz[q] = (uint32_t)((lr*8 + ((g0 + q) ^ (lr & 7))) * 16);

    // ---- warp tiling: 2(m) x 4(n), warp tile 64x32
    int warp_m = wid & 1;
    int warp_n = wid >> 1;

    int rAq[4];
#pragma unroll
    for (int mt = 0; mt < 4; mt++) rAq[mt] = warp_m*64 + mt*16 + (lane & 15);
    int cAoff = lane >> 4;
    int rBq[2];
#pragma unroll
    for (int np = 0; np < 2; np++) rBq[np] = warp_n*32 + np*16 + ((lane >> 4) << 3) + (lane & 7);
    int cBoff = (lane >> 3) & 1;

    float acc[4][4][4];
#pragma unroll
    for (int mt = 0; mt < 4; mt++)
#pragma unroll
        for (int nt = 0; nt < 4; nt++)
#pragma unroll
            for (int q = 0; q < 4; q++) acc[mt][nt][q] = 0.f;

    int NC = Kp / BK;

    // prologue: stages 0, 1
#pragma unroll
    for (int s = 0; s < 2; s++) {
        uint32_t sb = base + s * STAGE_SZ;
        long ko = (long)s * 128;
#pragma unroll
        for (int q = 0; q < 4; q++) CP16(sb + aswz[q],          gAp + ko + q*16);
#pragma unroll
        for (int q = 0; q < 4; q++) CP16(sb + SB_OFF + aswz[q], gBp + ko + q*16);
        CP_COMMIT();
    }

    uint32_t stage_of[3] = { base, base + STAGE_SZ, base + 2*STAGE_SZ };
    int s_c = 0, s_nn = 2;   // stage index of chunk c, and of chunk c+2

    for (int c = 0; c < NC; c++) {
        if (c + 2 < NC) {
            uint32_t sb = stage_of[s_nn];
            long ko = (long)(c + 2) * 128;
#pragma unroll
            for (int q = 0; q < 4; q++) CP16(sb + aswz[q],          gAp + ko + q*16);
#pragma unroll
            for (int q = 0; q < 4; q++) CP16(sb + SB_OFF + aswz[q], gBp + ko + q*16);
            CP_COMMIT();
            asm volatile("cp.async.wait_group 2;" ::: "memory");
        } else if (c + 1 < NC) {
            asm volatile("cp.async.wait_group 1;" ::: "memory");
        } else {
            asm volatile("cp.async.wait_group 0;" ::: "memory");
        }
        __syncthreads();

        uint32_t sA = stage_of[s_c];
        uint32_t sB = sA + SB_OFF;

#pragma unroll
        for (int kk = 0; kk < 4; kk++) {
            uint32_t a[4][4], b[4][2];
            int cA = kk*2 + cAoff;
#pragma unroll
            for (int mt = 0; mt < 4; mt++) {
                int r = rAq[mt];
                uint32_t ad = sA + (uint32_t)((r*8 + (cA ^ (r & 7))) * 16);
                LDSM_X4(a[mt][0], a[mt][1], a[mt][2], a[mt][3], ad);
            }
            int cB = kk*2 + cBoff;
#pragma unroll
            for (int np = 0; np < 2; np++) {
                int r = rBq[np];
                uint32_t bd = sB + (uint32_t)((r*8 + (cB ^ (r & 7))) * 16);
                LDSM_X4(b[2*np][0], b[2*np][1], b[2*np+1][0], b[2*np+1][1], bd);
            }
#pragma unroll
            for (int mt = 0; mt < 4; mt++)
#pragma unroll
                for (int nt = 0; nt < 4; nt++)
                    MMA16816(acc[mt][nt], a[mt][0], a[mt][1], a[mt][2], a[mt][3],
                             b[nt][0], b[nt][1]);
        }
        __syncthreads();

        s_c  = (s_c  == 2) ? 0 : s_c  + 1;
        s_nn = (s_nn == 2) ? 0 : s_nn + 1;
    }

    // ---- epilogue
#pragma unroll
    for (int mt = 0; mt < 4; mt++) {
        int r0 = m0 + warp_m*64 + mt*16 + (lane >> 2);
        int r1 = r0 + 8;
        size_t o0 = (size_t)r0 * ldc;
        size_t o1 = (size_t)r1 * ldc;
#pragma unroll
        for (int nt = 0; nt < 4; nt++) {
            int col = n0 + warp_n*32 + nt*8 + (lane & 3)*2;
            if (col >= N) continue;
            float v0 = acc[mt][nt][0], v1 = acc[mt][nt][1];
            float v2 = acc[mt][nt][2], v3 = acc[mt][nt][3];
            if (bias)  { float b0 = bias[col], b1 = bias[col+1];
                         v0 += b0; v1 += b1; v2 += b0; v3 += b1; }
            if (resid) { const float2 q0 = *(const float2*)(resid + o0 + col);
                         const float2 q1 = *(const float2*)(resid + o1 + col);
                         v0 += q0.x; v1 += q0.y; v2 += q1.x; v3 += q1.y; }
            *(float2*)(C + o0 + col) = make_float2(v0, v1);
            *(float2*)(C + o1 + col) = make_float2(v2, v3);
        }
    }
}

// ================= split conversions =================
__global__ void convA_k(const float* __restrict__ src, int K, int Kpad, long ldd,
                        __nv_bfloat16* __restrict__ dst)
{
    long idx = (long)blockIdx.x * blockDim.x + threadIdx.x;
    long tot = (long)BQ * Kpad;
    if (idx >= tot) return;
    int m = (int)(idx / Kpad), k = (int)(idx % Kpad);
    float v = (k < K) ? src[(long)m * K + k] : 0.f;
    __nv_bfloat16 hi = __float2bfloat16(v);
    __nv_bfloat16 lo = __float2bfloat16(v - __bfloat162float(hi));
    __nv_bfloat16* row = dst + (long)m * ldd;
    row[k] = hi; row[Kpad + k] = lo; row[2*Kpad + k] = hi;
}

__global__ void convW_k(const float* __restrict__ W, int K, int N, int Kpad, int Npad,
                        long ldd, __nv_bfloat16* __restrict__ dst)
{
    __shared__ float t[32][33];
    int k0 = blockIdx.x * 32, nn0 = blockIdx.y * 32;
    int tx = threadIdx.x, ty = threadIdx.y;   // (32, 8)
#pragma unroll
    for (int i = ty; i < 32; i += 8) {
        int k = k0 + i, n = nn0 + tx;
        t[i][tx] = (k < K && n < N) ? W[(long)k * N + n] : 0.f;
    }
    __syncthreads();
#pragma unroll
    for (int i = ty; i < 32; i += 8) {
        int n = nn0 + i;
        if (n >= Npad) continue;
        int k = k0 + tx;
        float v = t[tx][i];
        __nv_bfloat16 hi = __float2bfloat16(v);
        __nv_bfloat16 lo = __float2bfloat16(v - __bfloat162float(hi));
        __nv_bfloat16* row = dst + (long)n * ldd;
        row[k] = hi; row[Kpad + k] = hi; row[2*Kpad + k] = lo;
    }
}

// ================= LayerNorm (eps = 2048) =================
__global__ void ln_kernel(const float* __restrict__ seq,
                          const float* __restrict__ sc,
                          const float* __restrict__ bi)
{
    int b = blockIdx.x, t = threadIdx.x;
    const float* row = seq + ((size_t)b << 11);
    float v[8]; float s = 0.f, sq = 0.f;
#pragma unroll
    for (int q = 0; q < 8; q++) { v[q] = row[q*256 + t]; s += v[q]; sq = fmaf(v[q], v[q], sq); }
    __shared__ float sh_s[8], sh_q[8];
    __shared__ float s_mu, s_inv;
#pragma unroll
    for (int o = 16; o; o >>= 1) {
        s  += __shfl_down_sync(0xffffffffu, s,  o);
        sq += __shfl_down_sync(0xffffffffu, sq, o);
    }
    int warp = t >> 5, lane = t & 31;
    if (lane == 0) { sh_s[warp] = s; sh_q[warp] = sq; }
    __syncthreads();
    if (t == 0) {
        float ts = 0.f, tq = 0.f;
        for (int w = 0; w < 8; w++) { ts += sh_s[w]; tq += sh_q[w]; }
        float mu = ts / 2048.f;
        float var = tq / 2048.f - mu*mu;
        s_mu = mu; s_inv = rsqrtf(var + 2048.0f);
    }
    __syncthreads();
    float mu = s_mu, inv = s_inv;
#pragma unroll
    for (int q = 0; q < 8; q++) {
        int col = q*256 + t;
        g_xt[((size_t)b << 11) + col] = (v[q] - mu) * inv * sc[col] + bi[col];
    }
}

// ================= gating + block-diag recurrence =================
__global__ void gate_kernel(
    const float* __restrict__ b_i, const float* __restrict__ b_f,
    const float* __restrict__ b_z, const float* __restrict__ b_o,
    const float* __restrict__ Riw, const float* __restrict__ Rib,
    const float* __restrict__ Rfw, const float* __restrict__ Rfb,
    const float* __restrict__ Rzw, const float* __restrict__ Rzb,
    const float* __restrict__ Row_, const float* __restrict__ Rob,
    const float* __restrict__ c_tm1, const float* __restrict__ n_tm1,
    const float* __restrict__ h_tm1, const float* __restrict__ m_tm1,
    float* __restrict__ out, int write_states)
{
    size_t idx = (size_t)blockIdx.x * blockDim.x + threadIdx.x;
    if (idx >= (size_t)N_ELE) return;
    int b = (int)(idx >> 11);
    int j = (int)(idx & 2047);
    int h = j >> 7;
    int rem = j & 127;
    int n = rem >> 3;
    int e = rem & 7;

    const float* hp = h_tm1 + ((size_t)b << 11) + (h << 7) + (n << 3);
    float hv[8];
#pragma unroll
    for (int d = 0; d < 8; d++) hv[d] = hp[d];
    int sb = n*8 + e;
    int wb = n*64 + e;
    float bi_ = Rib[sb], bf_ = Rfb[sb], bz_ = Rzb[sb], bo_ = Rob[sb];
#pragma unroll
    for (int d = 0; d < 8; d++) {
        float hd = hv[d];
        bi_ = fmaf(hd, Riw[wb + d*8], bi_);
        bf_ = fmaf(hd, Rfw[wb + d*8], bf_);
        bz_ = fmaf(hd, Rzw[wb + d*8], bz_);
        bo_ = fmaf(hd, Row_[wb + d*8], bo_);
    }

    float it = g_gates[idx]                    + b_i[j] + bi_;
    float ft = g_gates[(size_t)N_ELE   + idx]  + b_f[j] + bf_;
    float zt = g_gates[(size_t)2*N_ELE + idx]  + b_z[j] + bz_;
    float ot = g_gates[(size_t)3*N_ELE + idx]  + b_o[j] + bo_;

    float mprev = m_tm1[idx];
    float mt = fmaxf(ft + mprev, it);
    float ie = expf(it - mt);
    float fe = expf(ft - mt + mprev);
    float z  = tanhf(zt);
    float ct = fe * c_tm1[idx] + ie * z;
    float nt = fe * n_tm1[idx] + ie;
    float o  = 1.f / (1.f + expf(-ot));
    float ht = o * (ct / nt);

    g_ht[idx] = ht;
    if (write_states) {
        out[(size_t)N_ELE   + idx] = ct;
        out[(size_t)2*N_ELE + idx] = nt;
        out[(size_t)3*N_ELE + idx] = ht;
        out[(size_t)4*N_ELE + idx] = mt;
    }
}

// ================= GroupNorm =================
__global__ void gn_kernel(const float* __restrict__ sc, const float* __restrict__ bi)
{
    int b = blockIdx.x, t = threadIdx.x;
    __shared__ float row[2048];
    __shared__ float ps[256], pq[256];
    __shared__ float gmu[16], gis[16];
    const float* hr = g_ht + ((size_t)b << 11);
#pragma unroll
    for (int q = 0; q < 8; q++) row[q*256 + t] = hr[q*256 + t];
    __syncthreads();

    int g = t >> 4, p = t & 15;
    float s = 0.f, sq = 0.f;
#pragma unroll
    for (int dg = 0; dg < 8; dg++) {
        float v = row[p*128 + g*8 + dg];
        s += v; sq = fmaf(v, v, sq);
    }
    ps[t] = s; pq[t] = sq;
    __syncthreads();
    for (int st = 8; st > 0; st >>= 1) {
        if (p < st) { ps[t] += ps[t + st]; pq[t] += pq[t + st]; }
        __syncthreads();
    }
    if (p == 0) {
        float mu = ps[t] / 128.f;
        float var = pq[t] / 128.f - mu*mu;
        gmu[g] = mu; gis[g] = rsqrtf(var + 1e-6f);
    }
    __syncthreads();
#pragma unroll
    for (int q = 0; q < 8; q++) {
        int col = q*256 + t;
        int hd = col & 127;
        int gg = hd >> 3;
        float v = (row[col] - gmu[gg]) * gis[gg];
        g_xt[((size_t)b << 11) + col] = v * sc[hd] + bi[hd];
    }
}

// ================= GLU =================
__global__ void glu_kernel()
{
    long idx = (long)blockIdx.x * blockDim.x + threadIdx.x;
    long tot = (long)BQ * PROJ;
    if (idx >= tot) return;
    int b = (int)(idx / PROJ);
    int j = (int)(idx % PROJ);
    const float* up = g_gates + (long)b * UPN;
    float a = up[j];
    float x = up[j + PROJ];
    float x3 = x * x * x;
    float gg = 0.5f * x * (1.f + tanhf(0.7978845608028654f * (x + 0.044715f * x3)));
    g_gated[idx] = a + gg;
}

// ================= driver =================
extern "C" void kernel_launch(void* const* d_in, const int* in_sizes, int n_in,
                              void* d_out, int out_size)
{
    const float* seq      = (const float*)d_in[0];
    const float* c_tm1    = (const float*)d_in[1];
    const float* n_tm1    = (const float*)d_in[2];
    const float* h_tm1    = (const float*)d_in[3];
    const float* m_tm1    = (const float*)d_in[4];
    const float* ln_scale = (const float*)d_in[5];
    const float* ln_bias  = (const float*)d_in[6];
    const float* W_z      = (const float*)d_in[7];
    const float* b_z      = (const float*)d_in[8];
    const float* W_i      = (const float*)d_in[9];
    const float* b_i      = (const float*)d_in[10];
    const float* W_f      = (const float*)d_in[11];
    const float* b_f      = (const float*)d_in[12];
    const float* W_o      = (const float*)d_in[13];
    const float* b_o      = (const float*)d_in[14];
    const float* R_z_w    = (const float*)d_in[15];
    const float* R_z_b    = (const float*)d_in[16];
    const float* R_i_w    = (const float*)d_in[17];
    const float* R_i_b    = (const float*)d_in[18];
    const float* R_f_w    = (const float*)d_in[19];
    const float* R_f_b    = (const float*)d_in[20];
    const float* R_o_w    = (const float*)d_in[21];
    const float* R_o_b    = (const float*)d_in[22];
    const float* gn_scale = (const float*)d_in[23];
    const float* gn_bias  = (const float*)d_in[24];
    const float* up_w     = (const float*)d_in[25];
    const float* up_b     = (const float*)d_in[26];
    const float* down_w   = (const float*)d_in[27];
    const float* down_b   = (const float*)d_in[28];
    float* out = (float*)d_out;

    int write_states = (out_size >= 5 * N_ELE) ? 1 : 0;

    cudaFuncSetAttribute(mma_gemm, cudaFuncAttributeMaxDynamicSharedMemorySize, SMEMSZ);

    void *pA, *pBg, *pBu, *pBd, *pXT, *pG, *pGated;
    cudaGetSymbolAddress(&pA,  gA);
    cudaGetSymbolAddress(&pBg, gBg);
    cudaGetSymbolAddress(&pBu, gBu);
    cudaGetSymbolAddress(&pBd, gBd);
    cudaGetSymbolAddress(&pXT, g_xt);
    cudaGetSymbolAddress(&pG,  g_gates);
    cudaGetSymbolAddress(&pGated, g_gated);
    __nv_bfloat16* A  = (__nv_bfloat16*)pA;
    __nv_bfloat16* Bg = (__nv_bfloat16*)pBg;
    __nv_bfloat16* Bu = (__nv_bfloat16*)pBu;
    __nv_bfloat16* Bd = (__nv_bfloat16*)pBd;
    float* xt    = (float*)pXT;
    float* gates = (float*)pG;
    float* gated = (float*)pGated;

    dim3 cw(32, 8);

    // weight conversions
    convW_k<<<dim3(KP1/32, DD/32), cw>>>(W_i, DD, DD, KP1, DD, LDA1, Bg + 0L*DD*LDA1);
    convW_k<<<dim3(KP1/32, DD/32), cw>>>(W_f, DD, DD, KP1, DD, LDA1, Bg + 1L*DD*LDA1);
    convW_k<<<dim3(KP1/32, DD/32), cw>>>(W_z, DD, DD, KP1, DD, LDA1, Bg + 2L*DD*LDA1);
    convW_k<<<dim3(KP1/32, DD/32), cw>>>(W_o, DD, DD, KP1, DD, LDA1, Bg + 3L*DD*LDA1);
    convW_k<<<dim3(KP1/32, NPAD_UP/32), cw>>>(up_w,   DD,   UPN, KP1, NPAD_UP, LDA1, Bu);
    convW_k<<<dim3(KP2/32, DD/32), cw>>>(down_w, PROJ, DD,  KP2, DD,      LDA2, Bd);

    // 1. LayerNorm
    ln_kernel<<<BQ, 256>>>(seq, ln_scale, ln_bias);

    // 2. split x_t
    convA_k<<<(unsigned)(((long)BQ*KP1 + 255)/256), 256>>>(xt, DD, KP1, LDA1, A);

    // 3. four gate GEMMs (batched over z): slabs [i,f,z,o]
    mma_gemm<<<dim3(DD/BN, BQ/BM, 4), 256, SMEMSZ>>>(
        A, LDA1, Bg, LDA1, gates, DD, DD, LDA1,
        (long)DD*LDA1, (long)N_ELE, nullptr, nullptr);

    // 4. gating + recurrence + states
    gate_kernel<<<N_ELE/256, 256>>>(b_i, b_f, b_z, b_o,
                                    R_i_w, R_i_b, R_f_w, R_f_b,
                                    R_z_w, R_z_b, R_o_w, R_o_b,
                                    c_tm1, n_tm1, h_tm1, m_tm1,
                                    out, write_states);

    // 5. GroupNorm -> g_xt
    gn_kernel<<<BQ, 256>>>(gn_scale, gn_bias);

    // 6. split GN output, up GEMM (+bias)
    convA_k<<<(unsigned)(((long)BQ*KP1 + 255)/256), 256>>>(xt, DD, KP1, LDA1, A);
    mma_gemm<<<dim3((UPN + BN - 1)/BN, BQ/BM, 1), 256, SMEMSZ>>>(
        A, LDA1, Bu, LDA1, gates, UPN, UPN, LDA1, 0, 0, up_b, nullptr);

    // 7. GLU
    glu_kernel<<<(unsigned)(((long)BQ*PROJ + 255)/256), 256>>>();

    // 8. split gated, down GEMM (+bias +residual)
    convA_k<<<(unsigned)(((long)BQ*KP2 + 255)/256), 256>>>(gated, PROJ, KP2, LDA2, A);
    mma_gemm<<<dim3(DD/BN, BQ/BM, 1), 256, SMEMSZ>>>(
        A, LDA2, Bd, LDA2, out, DD, DD, LDA2, 0, 0, down_b, seq);
}

// round 6
// speedup vs baseline: 1.4264x; 1.1790x over previous
#include <cuda_runtime.h>
#include <cuda_bf16.h>
#include <cstdint>
#include <math.h>

// ================= problem constants =================
#define BQ   4096
#define DD   2048
#define PROJ 2730
#define UPN  5460
#define N_ELE (BQ*DD)

// split-bf16 K layouts: K' = 3*Kpad, segments [A_hi | A_lo | A_hi] x [B_hi | B_hi | B_lo]
#define KP1   2048            // gates / up
#define LDA1  (3*KP1)         // 6144
#define KP2   2752            // down (2730 padded to mult of 64)
#define LDA2  (3*KP2)         // 8256
#define NPAD_UP 5632

// ================= scratch (static device globals) =================
__device__ __align__(256) __nv_bfloat16 gA [(size_t)BQ*LDA2];
__device__ __align__(256) __nv_bfloat16 gBg[(size_t)4*DD*LDA1];
__device__ __align__(256) __nv_bfloat16 gBu[(size_t)NPAD_UP*LDA1];
__device__ __align__(256) __nv_bfloat16 gBd[(size_t)DD*LDA2];
__device__ __align__(16) float g_xt[N_ELE];
__device__ __align__(16) float g_gates[(size_t)4*N_ELE];
__device__ __align__(16) float g_ht[N_ELE];
__device__ __align__(16) float g_gated[(size_t)BQ*PROJ];

// ================= PTX helpers =================
__device__ __forceinline__ uint32_t smem_u32(const void* p){
    uint32_t a; asm("{ .reg .u64 t; cvta.to.shared.u64 t, %1; cvt.u32.u64 %0, t; }" : "=r"(a) : "l"(p));
    return a;
}
#define CP16(s, g) asm volatile("cp.async.cg.shared.global [%0], [%1], 16;" :: "r"(s), "l"(g) : "memory")
#define CP_COMMIT() asm volatile("cp.async.commit_group;" ::: "memory")

#define LDSM_X4(r0,r1,r2,r3,addr) \
    asm volatile("ldmatrix.sync.aligned.m8n8.x4.shared.b16 {%0,%1,%2,%3}, [%4];" \
        : "=r"(r0), "=r"(r1), "=r"(r2), "=r"(r3) : "r"(addr))
#define MMA16816(d, a0,a1,a2,a3, b0,b1) \
    asm volatile("mma.sync.aligned.m16n8k16.row.col.f32.bf16.bf16.f32 " \
        "{%0,%1,%2,%3}, {%4,%5,%6,%7}, {%8,%9}, {%0,%1,%2,%3};" \
        : "+f"((d)[0]), "+f"((d)[1]), "+f"((d)[2]), "+f"((d)[3]) \
        : "r"(a0), "r"(a1), "r"(a2), "r"(a3), "r"(b0), "r"(b1))

// ================= HMMA GEMM: C[M,N] = A[M,K'] * Bt[N,K']^T =================
// CTA tile 128x128x64, 8 warps (2m x 4n), warp tile 64x32, 3-stage cp.async,
// ONE barrier per chunk (cp.async issue moved after compute), 2 CTAs/SM.
#define BM 128
#define BN 128
#define BK 64
#define SB_OFF    16384u
#define STAGE_SZ  32768u
#define SMEMSZ    98304

__global__ void __launch_bounds__(256, 2) mma_gemm(
    const __nv_bfloat16* __restrict__ A, long lda,
    const __nv_bfloat16* __restrict__ B, long ldb,
    float* __restrict__ C, int N, int ldc, int Kp,
    long bStride, long cStride,
    const float* __restrict__ bias,
    const float* __restrict__ resid)
{
    extern __shared__ __align__(1024) char smem[];
    uint32_t base = smem_u32(smem);

    int tid  = threadIdx.x;
    int lane = tid & 31;
    int wid  = tid >> 5;
    int n0 = blockIdx.x * BN;
    int m0 = blockIdx.y * BM;
    B += (long)blockIdx.z * bStride;
    C += (long)blockIdx.z * cStride;

    // ---- loader slots: row = tid>>1 (0..127), 4 granules starting at (tid&1)*4
    int lr  = tid >> 1;
    int g0  = (tid & 1) * 4;
    const char* gAp = (const char*)(A + (long)(m0 + lr) * lda) + g0*16;
    const char* gBp = (const char*)(B + (long)(n0 + lr) * ldb) + g0*16;
    uint32_t aswz[4];
#pragma unroll
    for (int q = 0; q < 4; q++)
        aswz[q] = (uint32_t)((lr*8 + ((g0 + q) ^ (lr & 7))) * 16);

    // ---- warp tiling: 2(m) x 4(n), warp tile 64x32
    int warp_m = wid & 1;
    int warp_n = wid >> 1;

    int rAq[4];
#pragma unroll
    for (int mt = 0; mt < 4; mt++) rAq[mt] = warp_m*64 + mt*16 + (lane & 15);
    int cAoff = lane >> 4;
    int rBq[2];
#pragma unroll
    for (int np = 0; np < 2; np++) rBq[np] = warp_n*32 + np*16 + ((lane >> 4) << 3) + (lane & 7);
    int cBoff = (lane >> 3) & 1;

    float acc[4][4][4];
#pragma unroll
    for (int mt = 0; mt < 4; mt++)
#pragma unroll
        for (int nt = 0; nt < 4; nt++)
#pragma unroll
            for (int q = 0; q < 4; q++) acc[mt][nt][q] = 0.f;

    int NC = Kp / BK;

    // prologue: chunks 0,1 -> stages 0,1
#pragma unroll
    for (int s = 0; s < 2; s++) {
        uint32_t sb = base + s * STAGE_SZ;
        long ko = (long)s * 128;
#pragma unroll
        for (int q = 0; q < 4; q++) CP16(sb + aswz[q],          gAp + ko + q*16);
#pragma unroll
        for (int q = 0; q < 4; q++) CP16(sb + SB_OFF + aswz[q], gBp + ko + q*16);
        CP_COMMIT();
    }

    uint32_t stage_of[3] = { base, base + STAGE_SZ, base + 2*STAGE_SZ };
    int s_c = 0, s_nn = 2;   // stage of chunk c / chunk c+2

    for (int c = 0; c < NC; c++) {
        if (c + 1 < NC) asm volatile("cp.async.wait_group 1;" ::: "memory");
        else            asm volatile("cp.async.wait_group 0;" ::: "memory");
        __syncthreads();   // single barrier per chunk

        uint32_t sA = stage_of[s_c];
        uint32_t sB = sA + SB_OFF;

#pragma unroll
        for (int kk = 0; kk < 4; kk++) {
            uint32_t a[4][4], b[4][2];
            int cA = kk*2 + cAoff;
#pragma unroll
            for (int mt = 0; mt < 4; mt++) {
                int r = rAq[mt];
                uint32_t ad = sA + (uint32_t)((r*8 + (cA ^ (r & 7))) * 16);
                LDSM_X4(a[mt][0], a[mt][1], a[mt][2], a[mt][3], ad);
            }
            int cB = kk*2 + cBoff;
#pragma unroll
            for (int np = 0; np < 2; np++) {
                int r = rBq[np];
                uint32_t bd = sB + (uint32_t)((r*8 + (cB ^ (r & 7))) * 16);
                LDSM_X4(b[2*np][0], b[2*np][1], b[2*np+1][0], b[2*np+1][1], bd);
            }
#pragma unroll
            for (int mt = 0; mt < 4; mt++)
#pragma unroll
                for (int nt = 0; nt < 4; nt++)
                    MMA16816(acc[mt][nt], a[mt][0], a[mt][1], a[mt][2], a[mt][3],
                             b[nt][0], b[nt][1]);
        }

        // issue chunk c+2 AFTER compute: its stage (c+2)%3 == (c-1)%3 was last
        // read in compute c-1, which the top-of-c barrier already ordered.
        if (c + 2 < NC) {
            uint32_t sb = stage_of[s_nn];
            long ko = (long)(c + 2) * 128;
#pragma unroll
            for (int q = 0; q < 4; q++) CP16(sb + aswz[q],          gAp + ko + q*16);
#pragma unroll
            for (int q = 0; q < 4; q++) CP16(sb + SB_OFF + aswz[q], gBp + ko + q*16);
            CP_COMMIT();
        }

        s_c  = (s_c  == 2) ? 0 : s_c  + 1;
        s_nn = (s_nn == 2) ? 0 : s_nn + 1;
    }

    // ---- epilogue
#pragma unroll
    for (int mt = 0; mt < 4; mt++) {
        int r0 = m0 + warp_m*64 + mt*16 + (lane >> 2);
        int r1 = r0 + 8;
        size_t o0 = (size_t)r0 * ldc;
        size_t o1 = (size_t)r1 * ldc;
#pragma unroll
        for (int nt = 0; nt < 4; nt++) {
            int col = n0 + warp_n*32 + nt*8 + (lane & 3)*2;
            if (col >= N) continue;
            float v0 = acc[mt][nt][0], v1 = acc[mt][nt][1];
            float v2 = acc[mt][nt][2], v3 = acc[mt][nt][3];
            if (bias)  { float b0 = bias[col], b1 = bias[col+1];
                         v0 += b0; v1 += b1; v2 += b0; v3 += b1; }
            if (resid) { const float2 q0 = *(const float2*)(resid + o0 + col);
                         const float2 q1 = *(const float2*)(resid + o1 + col);
                         v0 += q0.x; v1 += q0.y; v2 += q1.x; v3 += q1.y; }
            *(float2*)(C + o0 + col) = make_float2(v0, v1);
            *(float2*)(C + o1 + col) = make_float2(v2, v3);
        }
    }
}

// ================= split conversions =================
__global__ void convA_k(const float* __restrict__ src, int K, int Kpad, long ldd,
                        __nv_bfloat16* __restrict__ dst)
{
    long idx = (long)blockIdx.x * blockDim.x + threadIdx.x;
    long tot = (long)BQ * Kpad;
    if (idx >= tot) return;
    int m = (int)(idx / Kpad), k = (int)(idx % Kpad);
    float v = (k < K) ? src[(long)m * K + k] : 0.f;
    __nv_bfloat16 hi = __float2bfloat16(v);
    __nv_bfloat16 lo = __float2bfloat16(v - __bfloat162float(hi));
    __nv_bfloat16* row = dst + (long)m * ldd;
    row[k] = hi; row[Kpad + k] = lo; row[2*Kpad + k] = hi;
}

__device__ __forceinline__ void convW_body(const float* W, int K, int N, int Kpad, int Npad,
                                           long ldd, __nv_bfloat16* dst)
{
    __shared__ float t[32][33];
    int k0 = blockIdx.x * 32, nn0 = blockIdx.y * 32;
    int tx = threadIdx.x, ty = threadIdx.y;   // (32, 8)
#pragma unroll
    for (int i = ty; i < 32; i += 8) {
        int k = k0 + i, n = nn0 + tx;
        t[i][tx] = (k < K && n < N) ? W[(long)k * N + n] : 0.f;
    }
    __syncthreads();
#pragma unroll
    for (int i = ty; i < 32; i += 8) {
        int n = nn0 + i;
        if (n >= Npad) continue;
        int k = k0 + tx;
        float v = t[tx][i];
        __nv_bfloat16 hi = __float2bfloat16(v);
        __nv_bfloat16 lo = __float2bfloat16(v - __bfloat162float(hi));
        __nv_bfloat16* row = dst + (long)n * ldd;
        row[k] = hi; row[Kpad + k] = hi; row[2*Kpad + k] = lo;
    }
}

__global__ void convW_k(const float* __restrict__ W, int K, int N, int Kpad, int Npad,
                        long ldd, __nv_bfloat16* __restrict__ dst)
{
    convW_body(W, K, N, Kpad, Npad, ldd, dst);
}

// batched gate-weight conversion: blockIdx.z selects among 4 weights
__global__ void convWg4_k(const float* __restrict__ W0, const float* __restrict__ W1,
                          const float* __restrict__ W2, const float* __restrict__ W3,
                          __nv_bfloat16* __restrict__ dst)
{
    const float* W = (blockIdx.z == 0) ? W0 : (blockIdx.z == 1) ? W1
                   : (blockIdx.z == 2) ? W2 : W3;
    convW_body(W, DD, DD, KP1, DD, LDA1, dst + (size_t)blockIdx.z * DD * LDA1);
}

// ================= LayerNorm (eps = 2048) =================
__global__ void ln_kernel(const float* __restrict__ seq,
                          const float* __restrict__ sc,
                          const float* __restrict__ bi)
{
    int b = blockIdx.x, t = threadIdx.x;
    const float* row = seq + ((size_t)b << 11);
    float v[8]; float s = 0.f, sq = 0.f;
#pragma unroll
    for (int q = 0; q < 8; q++) { v[q] = row[q*256 + t]; s += v[q]; sq = fmaf(v[q], v[q], sq); }
    __shared__ float sh_s[8], sh_q[8];
    __shared__ float s_mu, s_inv;
#pragma unroll
    for (int o = 16; o; o >>= 1) {
        s  += __shfl_down_sync(0xffffffffu, s,  o);
        sq += __shfl_down_sync(0xffffffffu, sq, o);
    }
    int warp = t >> 5, lane = t & 31;
    if (lane == 0) { sh_s[warp] = s; sh_q[warp] = sq; }
    __syncthreads();
    if (t == 0) {
        float ts = 0.f, tq = 0.f;
        for (int w = 0; w < 8; w++) { ts += sh_s[w]; tq += sh_q[w]; }
        float mu = ts / 2048.f;
        float var = tq / 2048.f - mu*mu;
        s_mu = mu; s_inv = rsqrtf(var + 2048.0f);
    }
    __syncthreads();
    float mu = s_mu, inv = s_inv;
#pragma unroll
    for (int q = 0; q < 8; q++) {
        int col = q*256 + t;
        g_xt[((size_t)b << 11) + col] = (v[q] - mu) * inv * sc[col] + bi[col];
    }
}

// ================= gating + block-diag recurrence =================
__global__ void gate_kernel(
    const float* __restrict__ b_i, const float* __restrict__ b_f,
    const float* __restrict__ b_z, const float* __restrict__ b_o,
    const float* __restrict__ Riw, const float* __restrict__ Rib,
    const float* __restrict__ Rfw, const float* __restrict__ Rfb,
    const float* __restrict__ Rzw, const float* __restrict__ Rzb,
    const float* __restrict__ Row_, const float* __restrict__ Rob,
    const float* __restrict__ c_tm1, const float* __restrict__ n_tm1,
    const float* __restrict__ h_tm1, const float* __restrict__ m_tm1,
    float* __restrict__ out, int write_states)
{
    size_t idx = (size_t)blockIdx.x * blockDim.x + threadIdx.x;
    if (idx >= (size_t)N_ELE) return;
    int b = (int)(idx >> 11);
    int j = (int)(idx & 2047);
    int h = j >> 7;
    int rem = j & 127;
    int n = rem >> 3;
    int e = rem & 7;

    const float* hp = h_tm1 + ((size_t)b << 11) + (h << 7) + (n << 3);
    float hv[8];
#pragma unroll
    for (int d = 0; d < 8; d++) hv[d] = hp[d];
    int sb = n*8 + e;
    int wb = n*64 + e;
    float bi_ = Rib[sb], bf_ = Rfb[sb], bz_ = Rzb[sb], bo_ = Rob[sb];
#pragma unroll
    for (int d = 0; d < 8; d++) {
        float hd = hv[d];
        bi_ = fmaf(hd, Riw[wb + d*8], bi_);
        bf_ = fmaf(hd, Rfw[wb + d*8], bf_);
        bz_ = fmaf(hd, Rzw[wb + d*8], bz_);
        bo_ = fmaf(hd, Row_[wb + d*8], bo_);
    }

    float it = g_gates[idx]                    + b_i[j] + bi_;
    float ft = g_gates[(size_t)N_ELE   + idx]  + b_f[j] + bf_;
    float zt = g_gates[(size_t)2*N_ELE + idx]  + b_z[j] + bz_;
    float ot = g_gates[(size_t)3*N_ELE + idx]  + b_o[j] + bo_;

    float mprev = m_tm1[idx];
    float mt = fmaxf(ft + mprev, it);
    float ie = expf(it - mt);
    float fe = expf(ft - mt + mprev);
    float z  = tanhf(zt);
    float ct = fe * c_tm1[idx] + ie * z;
    float nt = fe * n_tm1[idx] + ie;
    float o  = 1.f / (1.f + expf(-ot));
    float ht = o * (ct / nt);

    g_ht[idx] = ht;
    if (write_states) {
        out[(size_t)N_ELE   + idx] = ct;
        out[(size_t)2*N_ELE + idx] = nt;
        out[(size_t)3*N_ELE + idx] = ht;
        out[(size_t)4*N_ELE + idx] = mt;
    }
}

// ================= GroupNorm =================
__global__ void gn_kernel(const float* __restrict__ sc, const float* __restrict__ bi)
{
    int b = blockIdx.x, t = threadIdx.x;
    __shared__ float row[2048];
    __shared__ float ps[256], pq[256];
    __shared__ float gmu[16], gis[16];
    const float* hr = g_ht + ((size_t)b << 11);
#pragma unroll
    for (int q = 0; q < 8; q++) row[q*256 + t] = hr[q*256 + t];
    __syncthreads();

    int g = t >> 4, p = t & 15;
    float s = 0.f, sq = 0.f;
#pragma unroll
    for (int dg = 0; dg < 8; dg++) {
        float v = row[p*128 + g*8 + dg];
        s += v; sq = fmaf(v, v, sq);
    }
    ps[t] = s; pq[t] = sq;
    __syncthreads();
    for (int st = 8; st > 0; st >>= 1) {
        if (p < st) { ps[t] += ps[t + st]; pq[t] += pq[t + st]; }
        __syncthreads();
    }
    if (p == 0) {
        float mu = ps[t] / 128.f;
        float var = pq[t] / 128.f - mu*mu;
        gmu[g] = mu; gis[g] = rsqrtf(var + 1e-6f);
    }
    __syncthreads();
#pragma unroll
    for (int q = 0; q < 8; q++) {
        int col = q*256 + t;
        int hd = col & 127;
        int gg = hd >> 3;
        float v = (row[col] - gmu[gg]) * gis[gg];
        g_xt[((size_t)b << 11) + col] = v * sc[hd] + bi[hd];
    }
}

// ================= GLU =================
__global__ void glu_kernel()
{
    long idx = (long)blockIdx.x * blockDim.x + threadIdx.x;
    long tot = (long)BQ * PROJ;
    if (idx >= tot) return;
    int b = (int)(idx / PROJ);
    int j = (int)(idx % PROJ);
    const float* up = g_gates + (long)b * UPN;
    float a = up[j];
    float x = up[j + PROJ];
    float x3 = x * x * x;
    float gg = 0.5f * x * (1.f + tanhf(0.7978845608028654f * (x + 0.044715f * x3)));
    g_gated[idx] = a + gg;
}

// ================= driver =================
extern "C" void kernel_launch(void* const* d_in, const int* in_sizes, int n_in,
                              void* d_out, int out_size)
{
    const float* seq      = (const float*)d_in[0];
    const float* c_tm1    = (const float*)d_in[1];
    const float* n_tm1    = (const float*)d_in[2];
    const float* h_tm1    = (const float*)d_in[3];
    const float* m_tm1    = (const float*)d_in[4];
    const float* ln_scale = (const float*)d_in[5];
    const float* ln_bias  = (const float*)d_in[6];
    const float* W_z      = (const float*)d_in[7];
    const float* b_z      = (const float*)d_in[8];
    const float* W_i      = (const float*)d_in[9];
    const float* b_i      = (const float*)d_in[10];
    const float* W_f      = (const float*)d_in[11];
    const float* b_f      = (const float*)d_in[12];
    const float* W_o      = (const float*)d_in[13];
    const float* b_o      = (const float*)d_in[14];
    const float* R_z_w    = (const float*)d_in[15];
    const float* R_z_b    = (const float*)d_in[16];
    const float* R_i_w    = (const float*)d_in[17];
    const float* R_i_b    = (const float*)d_in[18];
    const float* R_f_w    = (const float*)d_in[19];
    const float* R_f_b    = (const float*)d_in[20];
    const float* R_o_w    = (const float*)d_in[21];
    const float* R_o_b    = (const float*)d_in[22];
    const float* gn_scale = (const float*)d_in[23];
    const float* gn_bias  = (const float*)d_in[24];
    const float* up_w     = (const float*)d_in[25];
    const float* up_b     = (const float*)d_in[26];
    const float* down_w   = (const float*)d_in[27];
    const float* down_b   = (const float*)d_in[28];
    float* out = (float*)d_out;

    int write_states = (out_size >= 5 * N_ELE) ? 1 : 0;

    cudaFuncSetAttribute(mma_gemm, cudaFuncAttributeMaxDynamicSharedMemorySize, SMEMSZ);

    void *pA, *pBg, *pBu, *pBd, *pXT, *pG, *pGated;
    cudaGetSymbolAddress(&pA,  gA);
    cudaGetSymbolAddress(&pBg, gBg);
    cudaGetSymbolAddress(&pBu, gBu);
    cudaGetSymbolAddress(&pBd, gBd);
    cudaGetSymbolAddress(&pXT, g_xt);
    cudaGetSymbolAddress(&pG,  g_gates);
    cudaGetSymbolAddress(&pGated, g_gated);
    __nv_bfloat16* A  = (__nv_bfloat16*)pA;
    __nv_bfloat16* Bg = (__nv_bfloat16*)pBg;
    __nv_bfloat16* Bu = (__nv_bfloat16*)pBu;
    __nv_bfloat16* Bd = (__nv_bfloat16*)pBd;
    float* xt    = (float*)pXT;
    float* gates = (float*)pG;
    float* gated = (float*)pGated;

    dim3 cw(32, 8);

    // launches #1-#5 (so that ncu's -s 5 -c 1 profiles the gate GEMM at #6)
    ln_kernel<<<BQ, 256>>>(seq, ln_scale, ln_bias);                                       // 1
    convA_k<<<(unsigned)(((long)BQ*KP1 + 255)/256), 256>>>(xt, DD, KP1, LDA1, A);         // 2
    convWg4_k<<<dim3(KP1/32, DD/32, 4), cw>>>(W_i, W_f, W_z, W_o, Bg);                    // 3
    convW_k<<<dim3(KP1/32, NPAD_UP/32), cw>>>(up_w,   DD,   UPN, KP1, NPAD_UP, LDA1, Bu); // 4
    convW_k<<<dim3(KP2/32, DD/32), cw>>>(down_w, PROJ, DD,  KP2, DD,      LDA2, Bd);      // 5

    // 6: four gate GEMMs (batched over z): slabs [i,f,z,o]   <- profiled launch
    mma_gemm<<<dim3(DD/BN, BQ/BM, 4), 256, SMEMSZ>>>(
        A, LDA1, Bg, LDA1, gates, DD, DD, LDA1,
        (long)DD*LDA1, (long)N_ELE, nullptr, nullptr);

    // gating + recurrence + states
    gate_kernel<<<N_ELE/256, 256>>>(b_i, b_f, b_z, b_o,
                                    R_i_w, R_i_b, R_f_w, R_f_b,
                                    R_z_w, R_z_b, R_o_w, R_o_b,
                                    c_tm1, n_tm1, h_tm1, m_tm1,
                                    out, write_states);

    // GroupNorm -> g_xt
    gn_kernel<<<BQ, 256>>>(gn_scale, gn_bias);

    // split GN output, up GEMM (+bias)
    convA_k<<<(unsigned)(((long)BQ*KP1 + 255)/256), 256>>>(xt, DD, KP1, LDA1, A);
    mma_gemm<<<dim3((UPN + BN - 1)/BN, BQ/BM, 1), 256, SMEMSZ>>>(
        A, LDA1, Bu, LDA1, gates, UPN, UPN, LDA1, 0, 0, up_b, nullptr);

    // GLU
    glu_kernel<<<(unsigned)(((long)BQ*PROJ + 255)/256), 256>>>();

    // split gated, down GEMM (+bias +residual)
    convA_k<<<(unsigned)(((long)BQ*KP2 + 255)/256), 256>>>(gated, PROJ, KP2, LDA2, A);
    mma_gemm<<<dim3(DD/BN, BQ/BM, 1), 256, SMEMSZ>>>(
        A, LDA2, Bd, LDA2, out, DD, DD, LDA2, 0, 0, down_b, seq);
}

// round 7
// speedup vs baseline: 2.1015x; 1.4733x over previous
#include <cuda_runtime.h>
#include <cuda_fp16.h>
#include <cstdint>
#include <math.h>

// ================= problem constants =================
#define BQ   4096
#define DD   2048
#define PROJ 2730
#define UPN  5460
#define N_ELE (BQ*DD)

// split-fp16 K layouts: K' = 2*Kpad, segments [A_hi | A_lo] x [B_hi | B_hi]
#define KP1   2048            // gates / up
#define LDA1  (2*KP1)         // 4096
#define KP2   2752            // down (2730 padded to mult of 64)
#define LDA2  (2*KP2)         // 5504
#define NPAD_UP 5632

// ================= scratch (static device globals) =================
__device__ __align__(256) __half gA [(size_t)BQ*LDA2];
__device__ __align__(256) __half gBg[(size_t)4*DD*LDA1];
__device__ __align__(256) __half gBu[(size_t)NPAD_UP*LDA1];
__device__ __align__(256) __half gBd[(size_t)DD*LDA2];
__device__ __align__(16) float g_gates[(size_t)4*N_ELE];   // gate preacts; reused for `up`
__device__ __align__(16) float g_ht[N_ELE];

// ================= PTX helpers =================
__device__ __forceinline__ uint32_t smem_u32(const void* p){
    uint32_t a; asm("{ .reg .u64 t; cvta.to.shared.u64 t, %1; cvt.u32.u64 %0, t; }" : "=r"(a) : "l"(p));
    return a;
}
#define CP16(s, g) asm volatile("cp.async.cg.shared.global [%0], [%1], 16;" :: "r"(s), "l"(g) : "memory")
#define CP_COMMIT() asm volatile("cp.async.commit_group;" ::: "memory")

#define LDSM_X4(r0,r1,r2,r3,addr) \
    asm volatile("ldmatrix.sync.aligned.m8n8.x4.shared.b16 {%0,%1,%2,%3}, [%4];" \
        : "=r"(r0), "=r"(r1), "=r"(r2), "=r"(r3) : "r"(addr))
#define MMA16816(d, a0,a1,a2,a3, b0,b1) \
    asm volatile("mma.sync.aligned.m16n8k16.row.col.f32.f16.f16.f32 " \
        "{%0,%1,%2,%3}, {%4,%5,%6,%7}, {%8,%9}, {%0,%1,%2,%3};" \
        : "+f"((d)[0]), "+f"((d)[1]), "+f"((d)[2]), "+f"((d)[3]) \
        : "r"(a0), "r"(a1), "r"(a2), "r"(a3), "r"(b0), "r"(b1))

__device__ __forceinline__ void split_h(float v, __half& hi, __half& lo){
    hi = __float2half(v);
    lo = __float2half(v - __half2float(hi));
}

// ================= HMMA GEMM: C[M,N] = A[M,K'] * Bt[N,K']^T =================
// CTA tile 128x128x64, 8 warps (2m x 4n), warp tile 64x32, 3-stage cp.async,
// single barrier per chunk, 2 CTAs/SM.
#define BM 128
#define BN 128
#define BK 64
#define SB_OFF    16384u
#define STAGE_SZ  32768u
#define SMEMSZ    98304

__global__ void __launch_bounds__(256, 2) mma_gemm(
    const __half* __restrict__ A, long lda,
    const __half* __restrict__ B, long ldb,
    float* __restrict__ C, int N, int ldc, int Kp,
    long bStride, long cStride,
    const float* __restrict__ bias,
    const float* __restrict__ resid)
{
    extern __shared__ __align__(1024) char smem[];
    uint32_t base = smem_u32(smem);

    int tid  = threadIdx.x;
    int lane = tid & 31;
    int wid  = tid >> 5;
    int n0 = blockIdx.x * BN;
    int m0 = blockIdx.y * BM;
    B += (long)blockIdx.z * bStride;
    C += (long)blockIdx.z * cStride;

    // ---- loader slots: row = tid>>1 (0..127), 4 granules starting at (tid&1)*4
    int lr  = tid >> 1;
    int g0  = (tid & 1) * 4;
    const char* gAp = (const char*)(A + (long)(m0 + lr) * lda) + g0*16;
    const char* gBp = (const char*)(B + (long)(n0 + lr) * ldb) + g0*16;
    uint32_t aswz[4];
#pragma unroll
    for (int q = 0; q < 4; q++)
        aswz[q] = (uint32_t)((lr*8 + ((g0 + q) ^ (lr & 7))) * 16);

    // ---- warp tiling: 2(m) x 4(n), warp tile 64x32
    int warp_m = wid & 1;
    int warp_n = wid >> 1;

    int rAq[4];
#pragma unroll
    for (int mt = 0; mt < 4; mt++) rAq[mt] = warp_m*64 + mt*16 + (lane & 15);
    int cAoff = lane >> 4;
    int rBq[2];
#pragma unroll
    for (int np = 0; np < 2; np++) rBq[np] = warp_n*32 + np*16 + ((lane >> 4) << 3) + (lane & 7);
    int cBoff = (lane >> 3) & 1;

    float acc[4][4][4];
#pragma unroll
    for (int mt = 0; mt < 4; mt++)
#pragma unroll
        for (int nt = 0; nt < 4; nt++)
#pragma unroll
            for (int q = 0; q < 4; q++) acc[mt][nt][q] = 0.f;

    int NC = Kp / BK;

    // prologue: chunks 0,1 -> stages 0,1
#pragma unroll
    for (int s = 0; s < 2; s++) {
        uint32_t sb = base + s * STAGE_SZ;
        long ko = (long)s * 128;
#pragma unroll
        for (int q = 0; q < 4; q++) CP16(sb + aswz[q],          gAp + ko + q*16);
#pragma unroll
        for (int q = 0; q < 4; q++) CP16(sb + SB_OFF + aswz[q], gBp + ko + q*16);
        CP_COMMIT();
    }

    uint32_t stage_of[3] = { base, base + STAGE_SZ, base + 2*STAGE_SZ };
    int s_c = 0, s_nn = 2;

    for (int c = 0; c < NC; c++) {
        if (c + 1 < NC) asm volatile("cp.async.wait_group 1;" ::: "memory");
        else            asm volatile("cp.async.wait_group 0;" ::: "memory");
        __syncthreads();

        uint32_t sA = stage_of[s_c];
        uint32_t sB = sA + SB_OFF;

#pragma unroll
        for (int kk = 0; kk < 4; kk++) {
            uint32_t a[4][4], b[4][2];
            int cA = kk*2 + cAoff;
#pragma unroll
            for (int mt = 0; mt < 4; mt++) {
                int r = rAq[mt];
                uint32_t ad = sA + (uint32_t)((r*8 + (cA ^ (r & 7))) * 16);
                LDSM_X4(a[mt][0], a[mt][1], a[mt][2], a[mt][3], ad);
            }
            int cB = kk*2 + cBoff;
#pragma unroll
            for (int np = 0; np < 2; np++) {
                int r = rBq[np];
                uint32_t bd = sB + (uint32_t)((r*8 + (cB ^ (r & 7))) * 16);
                LDSM_X4(b[2*np][0], b[2*np][1], b[2*np+1][0], b[2*np+1][1], bd);
            }
#pragma unroll
            for (int mt = 0; mt < 4; mt++)
#pragma unroll
                for (int nt = 0; nt < 4; nt++)
                    MMA16816(acc[mt][nt], a[mt][0], a[mt][1], a[mt][2], a[mt][3],
                             b[nt][0], b[nt][1]);
        }

        if (c + 2 < NC) {
            uint32_t sb = stage_of[s_nn];
            long ko = (long)(c + 2) * 128;
#pragma unroll
            for (int q = 0; q < 4; q++) CP16(sb + aswz[q],          gAp + ko + q*16);
#pragma unroll
            for (int q = 0; q < 4; q++) CP16(sb + SB_OFF + aswz[q], gBp + ko + q*16);
            CP_COMMIT();
        }

        s_c  = (s_c  == 2) ? 0 : s_c  + 1;
        s_nn = (s_nn == 2) ? 0 : s_nn + 1;
    }

    // ---- epilogue
#pragma unroll
    for (int mt = 0; mt < 4; mt++) {
        int r0 = m0 + warp_m*64 + mt*16 + (lane >> 2);
        int r1 = r0 + 8;
        size_t o0 = (size_t)r0 * ldc;
        size_t o1 = (size_t)r1 * ldc;
#pragma unroll
        for (int nt = 0; nt < 4; nt++) {
            int col = n0 + warp_n*32 + nt*8 + (lane & 3)*2;
            if (col >= N) continue;
            float v0 = acc[mt][nt][0], v1 = acc[mt][nt][1];
            float v2 = acc[mt][nt][2], v3 = acc[mt][nt][3];
            if (bias)  { float b0 = bias[col], b1 = bias[col+1];
                         v0 += b0; v1 += b1; v2 += b0; v3 += b1; }
            if (resid) { const float2 q0 = *(const float2*)(resid + o0 + col);
                         const float2 q1 = *(const float2*)(resid + o1 + col);
                         v0 += q0.x; v1 += q0.y; v2 += q1.x; v3 += q1.y; }
            *(float2*)(C + o0 + col) = make_float2(v0, v1);
            *(float2*)(C + o1 + col) = make_float2(v2, v3);
        }
    }
}

// ================= weight conversion: W[K,N] -> Bt[Npad, 2*Kpad], row = [hi|hi] =================
__device__ __forceinline__ void convW_body(const float* W, int K, int N, int Kpad, int Npad,
                                           long ldd, __half* dst)
{
    __shared__ float t[32][33];
    int k0 = blockIdx.x * 32, nn0 = blockIdx.y * 32;
    int tx = threadIdx.x, ty = threadIdx.y;   // (32, 8)
#pragma unroll
    for (int i = ty; i < 32; i += 8) {
        int k = k0 + i, n = nn0 + tx;
        t[i][tx] = (k < K && n < N) ? W[(long)k * N + n] : 0.f;
    }
    __syncthreads();
#pragma unroll
    for (int i = ty; i < 32; i += 8) {
        int n = nn0 + i;
        if (n >= Npad) continue;
        int k = k0 + tx;
        __half hi = __float2half(t[tx][i]);
        __half* row = dst + (long)n * ldd;
        row[k] = hi; row[Kpad + k] = hi;
    }
}

__global__ void convW_k(const float* __restrict__ W, int K, int N, int Kpad, int Npad,
                        long ldd, __half* __restrict__ dst)
{
    convW_body(W, K, N, Kpad, Npad, ldd, dst);
}

__global__ void convWg4_k(const float* __restrict__ W0, const float* __restrict__ W1,
                          const float* __restrict__ W2, const float* __restrict__ W3,
                          __half* __restrict__ dst)
{
    const float* W = (blockIdx.z == 0) ? W0 : (blockIdx.z == 1) ? W1
                   : (blockIdx.z == 2) ? W2 : W3;
    convW_body(W, DD, DD, KP1, DD, LDA1, dst + (size_t)blockIdx.z * DD * LDA1);
}

// ================= LayerNorm (eps = 2048), writes split-fp16 A directly =================
__global__ void ln_kernel(const float* __restrict__ seq,
                          const float* __restrict__ sc,
                          const float* __restrict__ bi)
{
    int b = blockIdx.x, t = threadIdx.x;
    const float* row = seq + ((size_t)b << 11);
    float v[8]; float s = 0.f, sq = 0.f;
#pragma unroll
    for (int q = 0; q < 8; q++) { v[q] = row[q*256 + t]; s += v[q]; sq = fmaf(v[q], v[q], sq); }
    __shared__ float sh_s[8], sh_q[8];
    __shared__ float s_mu, s_inv;
#pragma unroll
    for (int o = 16; o; o >>= 1) {
        s  += __shfl_down_sync(0xffffffffu, s,  o);
        sq += __shfl_down_sync(0xffffffffu, sq, o);
    }
    int warp = t >> 5, lane = t & 31;
    if (lane == 0) { sh_s[warp] = s; sh_q[warp] = sq; }
    __syncthreads();
    if (t == 0) {
        float ts = 0.f, tq = 0.f;
        for (int w = 0; w < 8; w++) { ts += sh_s[w]; tq += sh_q[w]; }
        float mu = ts / 2048.f;
        float var = tq / 2048.f - mu*mu;
        s_mu = mu; s_inv = rsqrtf(var + 2048.0f);
    }
    __syncthreads();
    float mu = s_mu, inv = s_inv;
    __half* arow = gA + (size_t)b * LDA1;
#pragma unroll
    for (int q = 0; q < 8; q++) {
        int col = q*256 + t;
        float x = (v[q] - mu) * inv * sc[col] + bi[col];
        __half hi, lo; split_h(x, hi, lo);
        arow[col] = hi; arow[KP1 + col] = lo;
    }
}

// ================= gating + block-diag recurrence =================
__global__ void gate_kernel(
    const float* __restrict__ b_i, const float* __restrict__ b_f,
    const float* __restrict__ b_z, const float* __restrict__ b_o,
    const float* __restrict__ Riw, const float* __restrict__ Rib,
    const float* __restrict__ Rfw, const float* __restrict__ Rfb,
    const float* __restrict__ Rzw, const float* __restrict__ Rzb,
    const float* __restrict__ Row_, const float* __restrict__ Rob,
    const float* __restrict__ c_tm1, const float* __restrict__ n_tm1,
    const float* __restrict__ h_tm1, const float* __restrict__ m_tm1,
    float* __restrict__ out, int write_states)
{
    size_t idx = (size_t)blockIdx.x * blockDim.x + threadIdx.x;
    if (idx >= (size_t)N_ELE) return;
    int b = (int)(idx >> 11);
    int j = (int)(idx & 2047);
    int h = j >> 7;
    int rem = j & 127;
    int n = rem >> 3;
    int e = rem & 7;

    const float* hp = h_tm1 + ((size_t)b << 11) + (h << 7) + (n << 3);
    float hv[8];
#pragma unroll
    for (int d = 0; d < 8; d++) hv[d] = hp[d];
    int sb = n*8 + e;
    int wb = n*64 + e;
    float bi_ = Rib[sb], bf_ = Rfb[sb], bz_ = Rzb[sb], bo_ = Rob[sb];
#pragma unroll
    for (int d = 0; d < 8; d++) {
        float hd = hv[d];
        bi_ = fmaf(hd, Riw[wb + d*8], bi_);
        bf_ = fmaf(hd, Rfw[wb + d*8], bf_);
        bz_ = fmaf(hd, Rzw[wb + d*8], bz_);
        bo_ = fmaf(hd, Row_[wb + d*8], bo_);
    }

    float it = g_gates[idx]                    + b_i[j] + bi_;
    float ft = g_gates[(size_t)N_ELE   + idx]  + b_f[j] + bf_;
    float zt = g_gates[(size_t)2*N_ELE + idx]  + b_z[j] + bz_;
    float ot = g_gates[(size_t)3*N_ELE + idx]  + b_o[j] + bo_;

    float mprev = m_tm1[idx];
    float mt = fmaxf(ft + mprev, it);
    float ie = expf(it - mt);
    float fe = expf(ft - mt + mprev);
    float z  = tanhf(zt);
    float ct = fe * c_tm1[idx] + ie * z;
    float nt = fe * n_tm1[idx] + ie;
    float o  = 1.f / (1.f + expf(-ot));
    float ht = o * (ct / nt);

    g_ht[idx] = ht;
    if (write_states) {
        out[(size_t)N_ELE   + idx] = ct;
        out[(size_t)2*N_ELE + idx] = nt;
        out[(size_t)3*N_ELE + idx] = ht;
        out[(size_t)4*N_ELE + idx] = mt;
    }
}

// ================= GroupNorm, writes split-fp16 A directly =================
__global__ void gn_kernel(const float* __restrict__ sc, const float* __restrict__ bi)
{
    int b = blockIdx.x, t = threadIdx.x;
    __shared__ float row[2048];
    __shared__ float ps[256], pq[256];
    __shared__ float gmu[16], gis[16];
    const float* hr = g_ht + ((size_t)b << 11);
#pragma unroll
    for (int q = 0; q < 8; q++) row[q*256 + t] = hr[q*256 + t];
    __syncthreads();

    int g = t >> 4, p = t & 15;
    float s = 0.f, sq = 0.f;
#pragma unroll
    for (int dg = 0; dg < 8; dg++) {
        float v = row[p*128 + g*8 + dg];
        s += v; sq = fmaf(v, v, sq);
    }
    ps[t] = s; pq[t] = sq;
    __syncthreads();
    for (int st = 8; st > 0; st >>= 1) {
        if (p < st) { ps[t] += ps[t + st]; pq[t] += pq[t + st]; }
        __syncthreads();
    }
    if (p == 0) {
        float mu = ps[t] / 128.f;
        float var = pq[t] / 128.f - mu*mu;
        gmu[g] = mu; gis[g] = rsqrtf(var + 1e-6f);
    }
    __syncthreads();
    __half* arow = gA + (size_t)b * LDA1;
#pragma unroll
    for (int q = 0; q < 8; q++) {
        int col = q*256 + t;
        int hd = col & 127;
        int gg = hd >> 3;
        float v = (row[col] - gmu[gg]) * gis[gg] * sc[hd] + bi[hd];
        __half hi, lo; split_h(v, hi, lo);
        arow[col] = hi; arow[KP1 + col] = lo;
    }
}

// ================= GLU, writes split-fp16 A (KP2 layout, zero-padded) =================
__global__ void glu_kernel()
{
    long idx = (long)blockIdx.x * blockDim.x + threadIdx.x;
    long tot = (long)BQ * KP2;
    if (idx >= tot) return;
    int b = (int)(idx / KP2);
    int j = (int)(idx % KP2);
    float r = 0.f;
    if (j < PROJ) {
        const float* up = g_gates + (long)b * UPN;
        float a = up[j];
        float x = up[j + PROJ];
        float x3 = x * x * x;
        float gg = 0.5f * x * (1.f + tanhf(0.7978845608028654f * (x + 0.044715f * x3)));
        r = a + gg;
    }
    __half hi, lo; split_h(r, hi, lo);
    __half* arow = gA + (long)b * LDA2;
    arow[j] = hi; arow[KP2 + j] = lo;
}

// ================= driver =================
extern "C" void kernel_launch(void* const* d_in, const int* in_sizes, int n_in,
                              void* d_out, int out_size)
{
    const float* seq      = (const float*)d_in[0];
    const float* c_tm1    = (const float*)d_in[1];
    const float* n_tm1    = (const float*)d_in[2];
    const float* h_tm1    = (const float*)d_in[3];
    const float* m_tm1    = (const float*)d_in[4];
    const float* ln_scale = (const float*)d_in[5];
    const float* ln_bias  = (const float*)d_in[6];
    const float* W_z      = (const float*)d_in[7];
    const float* b_z      = (const float*)d_in[8];
    const float* W_i      = (const float*)d_in[9];
    const float* b_i      = (const float*)d_in[10];
    const float* W_f      = (const float*)d_in[11];
    const float* b_f      = (const float*)d_in[12];
    const float* W_o      = (const float*)d_in[13];
    const float* b_o      = (const float*)d_in[14];
    const float* R_z_w    = (const float*)d_in[15];
    const float* R_z_b    = (const float*)d_in[16];
    const float* R_i_w    = (const float*)d_in[17];
    const float* R_i_b    = (const float*)d_in[18];
    const float* R_f_w    = (const float*)d_in[19];
    const float* R_f_b    = (const float*)d_in[20];
    const float* R_o_w    = (const float*)d_in[21];
    const float* R_o_b    = (const float*)d_in[22];
    const float* gn_scale = (const float*)d_in[23];
    const float* gn_bias  = (const float*)d_in[24];
    const float* up_w     = (const float*)d_in[25];
    const float* up_b     = (const float*)d_in[26];
    const float* down_w   = (const float*)d_in[27];
    const float* down_b   = (const float*)d_in[28];
    float* out = (float*)d_out;

    int write_states = (out_size >= 5 * N_ELE) ? 1 : 0;

    cudaFuncSetAttribute(mma_gemm, cudaFuncAttributeMaxDynamicSharedMemorySize, SMEMSZ);

    void *pA, *pBg, *pBu, *pBd, *pG;
    cudaGetSymbolAddress(&pA,  gA);
    cudaGetSymbolAddress(&pBg, gBg);
    cudaGetSymbolAddress(&pBu, gBu);
    cudaGetSymbolAddress(&pBd, gBd);
    cudaGetSymbolAddress(&pG,  g_gates);
    __half* A  = (__half*)pA;
    __half* Bg = (__half*)pBg;
    __half* Bu = (__half*)pBu;
    __half* Bd = (__half*)pBd;
    float* gates = (float*)pG;

    dim3 cw(32, 8);

    // conversions + LN (fused split)
    ln_kernel<<<BQ, 256>>>(seq, ln_scale, ln_bias);
    convWg4_k<<<dim3(KP1/32, DD/32, 4), cw>>>(W_i, W_f, W_z, W_o, Bg);
    convW_k<<<dim3(KP1/32, NPAD_UP/32), cw>>>(up_w,   DD,   UPN, KP1, NPAD_UP, LDA1, Bu);
    convW_k<<<dim3(KP2/32, DD/32), cw>>>(down_w, PROJ, DD,  KP2, DD,      LDA2, Bd);

    // four gate GEMMs (batched over z): slabs [i,f,z,o]
    mma_gemm<<<dim3(DD/BN, BQ/BM, 4), 256, SMEMSZ>>>(
        A, LDA1, Bg, LDA1, gates, DD, DD, LDA1,
        (long)DD*LDA1, (long)N_ELE, nullptr, nullptr);

    // gating + recurrence + states
    gate_kernel<<<N_ELE/256, 256>>>(b_i, b_f, b_z, b_o,
                                    R_i_w, R_i_b, R_f_w, R_f_b,
                                    R_z_w, R_z_b, R_o_w, R_o_b,
                                    c_tm1, n_tm1, h_tm1, m_tm1,
                                    out, write_states);

    // GroupNorm -> split A
    gn_kernel<<<BQ, 256>>>(gn_scale, gn_bias);

    // up GEMM (+bias)
    mma_gemm<<<dim3((UPN + BN - 1)/BN, BQ/BM, 1), 256, SMEMSZ>>>(
        A, LDA1, Bu, LDA1, gates, UPN, UPN, LDA1, 0, 0, up_b, nullptr);

    // GLU -> split A (KP2 layout)
    glu_kernel<<<(unsigned)(((long)BQ*KP2 + 255)/256), 256>>>();

    // down GEMM (+bias +residual)
    mma_gemm<<<dim3(DD/BN, BQ/BM, 1), 256, SMEMSZ>>>(
        A, LDA2, Bd, LDA2, out, DD, DD, LDA2, 0, 0, down_b, seq);
}

// round 8
// speedup vs baseline: 2.3534x; 1.1199x over previous
#include <cuda_runtime.h>
#include <cuda_fp16.h>
#include <cstdint>
#include <math.h>

// ================= problem constants =================
#define BQ   4096
#define DD   2048
#define PROJ 2730
#define UPN  5460
#define N_ELE (BQ*DD)

// split-fp16: A rows = [hi(Kpad) | lo(Kpad)]; B stored ONCE (hi), reused for both passes
#define KP1   2048            // gates / up
#define LDA1  (2*KP1)
#define KP2   2752            // down (2730 padded to mult of 32)
#define LDA2  (2*KP2)
#define NPAD_UP 5632

// ================= scratch (static device globals) =================
__device__ __align__(256) __half gA [(size_t)BQ*LDA2];
__device__ __align__(256) __half gBg[(size_t)4*DD*KP1];
__device__ __align__(256) __half gBu[(size_t)NPAD_UP*KP1];
__device__ __align__(256) __half gBd[(size_t)DD*KP2];
__device__ __align__(16) float g_gates[(size_t)4*N_ELE];   // gate preacts; reused for `up`
__device__ __align__(16) float g_ht[N_ELE];

// ================= PTX helpers =================
__device__ __forceinline__ uint32_t smem_u32(const void* p){
    uint32_t a; asm("{ .reg .u64 t; cvta.to.shared.u64 t, %1; cvt.u32.u64 %0, t; }" : "=r"(a) : "l"(p));
    return a;
}
#define CP16(s, g) asm volatile("cp.async.cg.shared.global [%0], [%1], 16;" :: "r"(s), "l"(g) : "memory")
#define CP_COMMIT() asm volatile("cp.async.commit_group;" ::: "memory")

#define LDSM_X4(r0,r1,r2,r3,addr) \
    asm volatile("ldmatrix.sync.aligned.m8n8.x4.shared.b16 {%0,%1,%2,%3}, [%4];" \
        : "=r"(r0), "=r"(r1), "=r"(r2), "=r"(r3) : "r"(addr))
#define MMA16816(d, a0,a1,a2,a3, b0,b1) \
    asm volatile("mma.sync.aligned.m16n8k16.row.col.f32.f16.f16.f32 " \
        "{%0,%1,%2,%3}, {%4,%5,%6,%7}, {%8,%9}, {%0,%1,%2,%3};" \
        : "+f"((d)[0]), "+f"((d)[1]), "+f"((d)[2]), "+f"((d)[3]) \
        : "r"(a0), "r"(a1), "r"(a2), "r"(a3), "r"(b0), "r"(b1))

__device__ __forceinline__ void split_h(float v, __half& hi, __half& lo){
    hi = __float2half(v);
    lo = __float2half(v - __half2float(hi));
}

// ================= HMMA GEMM: C = (A_hi + A_lo)[M,K] * Bt[N,K]^T =================
// K chunk = 32 real K. Stage = {A_hi 128x32, A_lo 128x32, B 128x32} = 24KB.
// 4 stages, single barrier/chunk, 8 warps (2m x 4n), warp tile 64x32, 2 CTAs/SM.
// SMEM tile rows are 64B (4 x 16B granules), swizzle g' = g ^ ((row>>1)&3).
#define BM 128
#define BN 128
#define BK 32
#define TILE_SZ   8192u
#define STAGE_SZ  24576u
#define SMEMSZ    98304

__global__ void __launch_bounds__(256, 2) mma_gemm(
    const __half* __restrict__ A, long lda,
    const __half* __restrict__ B, long ldb,
    float* __restrict__ C, int N, int ldc, int Kp,
    long bStride, long cStride,
    const float* __restrict__ bias,
    const float* __restrict__ resid)
{
    extern __shared__ __align__(1024) char smem[];
    uint32_t base = smem_u32(smem);

    int tid  = threadIdx.x;
    int lane = tid & 31;
    int wid  = tid >> 5;
    int n0 = blockIdx.x * BN;
    int m0 = blockIdx.y * BM;
    B += (long)blockIdx.z * bStride;
    C += (long)blockIdx.z * cStride;

    // ---- loader slots: row = tid>>1, granules (tid&1)*2 .. +1 (of 4 per 64B row)
    int lr  = tid >> 1;
    int g0  = (tid & 1) * 2;
    const char* gAhi = (const char*)(A + (long)(m0 + lr) * lda) + g0*16;
    const char* gAlo = gAhi + (long)Kp * 2;            // lo segment starts at Kp halves
    const char* gB   = (const char*)(B + (long)(n0 + lr) * ldb) + g0*16;
    uint32_t swz[2];
#pragma unroll
    for (int q = 0; q < 2; q++)
        swz[q] = (uint32_t)((lr*4 + ((g0 + q) ^ ((lr >> 1) & 3))) * 16);

    // ---- warp tiling: 2(m) x 4(n), warp tile 64x32
    int warp_m = wid & 1;
    int warp_n = wid >> 1;

    int rAq[4];
#pragma unroll
    for (int mt = 0; mt < 4; mt++) rAq[mt] = warp_m*64 + mt*16 + (lane & 15);
    int cAoff = lane >> 4;
    int rBq[2];
#pragma unroll
    for (int np = 0; np < 2; np++) rBq[np] = warp_n*32 + np*16 + ((lane >> 4) << 3) + (lane & 7);
    int cBoff = (lane >> 3) & 1;

    float acc[4][4][4];
#pragma unroll
    for (int mt = 0; mt < 4; mt++)
#pragma unroll
        for (int nt = 0; nt < 4; nt++)
#pragma unroll
            for (int q = 0; q < 4; q++) acc[mt][nt][q] = 0.f;

    int NC = Kp / BK;

    // prologue: chunks 0,1,2 -> stages 0,1,2
#pragma unroll
    for (int s = 0; s < 3; s++) {
        uint32_t sb = base + s * STAGE_SZ;
        long ko = (long)s * 64;    // 32 halves = 64B per row per chunk
#pragma unroll
        for (int q = 0; q < 2; q++) {
            CP16(sb +              swz[q], gAhi + ko + q*16);
            CP16(sb + TILE_SZ    + swz[q], gAlo + ko + q*16);
            CP16(sb + 2*TILE_SZ  + swz[q], gB   + ko + q*16);
        }
        CP_COMMIT();
    }

    uint32_t stage_of[4] = { base, base + STAGE_SZ, base + 2*STAGE_SZ, base + 3*STAGE_SZ };
    int s_c = 0, s_nn = 3;   // stage of chunk c / chunk c+3

    for (int c = 0; c < NC; c++) {
        int rem = NC - c - 1;          // chunks after c
        if (rem >= 2)      asm volatile("cp.async.wait_group 2;" ::: "memory");
        else if (rem == 1) asm volatile("cp.async.wait_group 1;" ::: "memory");
        else               asm volatile("cp.async.wait_group 0;" ::: "memory");
        __syncthreads();

        uint32_t sAh = stage_of[s_c];
        uint32_t sAl = sAh + TILE_SZ;
        uint32_t sB  = sAh + 2*TILE_SZ;

#pragma unroll
        for (int kk = 0; kk < 2; kk++) {
            uint32_t a[4][4], b[4][2];
            int cB = kk*2 + cBoff;
#pragma unroll
            for (int np = 0; np < 2; np++) {
                int r = rBq[np];
                uint32_t bd = sB + (uint32_t)((r*4 + (cB ^ ((r >> 1) & 3))) * 16);
                LDSM_X4(b[2*np][0], b[2*np][1], b[2*np+1][0], b[2*np+1][1], bd);
            }
            int cA = kk*2 + cAoff;
            // hi pass
#pragma unroll
            for (int mt = 0; mt < 4; mt++) {
                int r = rAq[mt];
                uint32_t ad = sAh + (uint32_t)((r*4 + (cA ^ ((r >> 1) & 3))) * 16);
                LDSM_X4(a[mt][0], a[mt][1], a[mt][2], a[mt][3], ad);
            }
#pragma unroll
            for (int mt = 0; mt < 4; mt++)
#pragma unroll
                for (int nt = 0; nt < 4; nt++)
                    MMA16816(acc[mt][nt], a[mt][0], a[mt][1], a[mt][2], a[mt][3],
                             b[nt][0], b[nt][1]);
            // lo pass (reuses a[] registers and b frags)
#pragma unroll
            for (int mt = 0; mt < 4; mt++) {
                int r = rAq[mt];
                uint32_t ad = sAl + (uint32_t)((r*4 + (cA ^ ((r >> 1) & 3))) * 16);
                LDSM_X4(a[mt][0], a[mt][1], a[mt][2], a[mt][3], ad);
            }
#pragma unroll
            for (int mt = 0; mt < 4; mt++)
#pragma unroll
                for (int nt = 0; nt < 4; nt++)
                    MMA16816(acc[mt][nt], a[mt][0], a[mt][1], a[mt][2], a[mt][3],
                             b[nt][0], b[nt][1]);
        }

        // issue chunk c+3 AFTER compute: its stage (c+3)%4 == (c-1)%4 was last
        // read in compute c-1, ordered by the barrier at the top of iteration c.
        if (c + 3 < NC) {
            uint32_t sb = stage_of[s_nn];
            long ko = (long)(c + 3) * 64;
#pragma unroll
            for (int q = 0; q < 2; q++) {
                CP16(sb +             swz[q], gAhi + ko + q*16);
                CP16(sb + TILE_SZ   + swz[q], gAlo + ko + q*16);
                CP16(sb + 2*TILE_SZ + swz[q], gB   + ko + q*16);
            }
            CP_COMMIT();
        }

        s_c  = (s_c  == 3) ? 0 : s_c  + 1;
        s_nn = (s_nn == 3) ? 0 : s_nn + 1;
    }

    // ---- epilogue
#pragma unroll
    for (int mt = 0; mt < 4; mt++) {
        int r0 = m0 + warp_m*64 + mt*16 + (lane >> 2);
        int r1 = r0 + 8;
        size_t o0 = (size_t)r0 * ldc;
        size_t o1 = (size_t)r1 * ldc;
#pragma unroll
        for (int nt = 0; nt < 4; nt++) {
            int col = n0 + warp_n*32 + nt*8 + (lane & 3)*2;
            if (col >= N) continue;
            float v0 = acc[mt][nt][0], v1 = acc[mt][nt][1];
            float v2 = acc[mt][nt][2], v3 = acc[mt][nt][3];
            if (bias)  { float b0 = bias[col], b1 = bias[col+1];
                         v0 += b0; v1 += b1; v2 += b0; v3 += b1; }
            if (resid) { const float2 q0 = *(const float2*)(resid + o0 + col);
                         const float2 q1 = *(const float2*)(resid + o1 + col);
                         v0 += q0.x; v1 += q0.y; v2 += q1.x; v3 += q1.y; }
            *(float2*)(C + o0 + col) = make_float2(v0, v1);
            *(float2*)(C + o1 + col) = make_float2(v2, v3);
        }
    }
}

// ================= weight conversion: W[K,N] -> Bt[Npad, Kpad] (hi only) =================
__device__ __forceinline__ void convW_body(const float* W, int K, int N, int Kpad, int Npad,
                                           long ldd, __half* dst)
{
    __shared__ float t[32][33];
    int k0 = blockIdx.x * 32, nn0 = blockIdx.y * 32;
    int tx = threadIdx.x, ty = threadIdx.y;   // (32, 8)
#pragma unroll
    for (int i = ty; i < 32; i += 8) {
        int k = k0 + i, n = nn0 + tx;
        t[i][tx] = (k < K && n < N) ? W[(long)k * N + n] : 0.f;
    }
    __syncthreads();
#pragma unroll
    for (int i = ty; i < 32; i += 8) {
        int n = nn0 + i;
        if (n >= Npad) continue;
        int k = k0 + tx;
        dst[(long)n * ldd + k] = __float2half(t[tx][i]);
    }
}

__global__ void convW_k(const float* __restrict__ W, int K, int N, int Kpad, int Npad,
                        long ldd, __half* __restrict__ dst)
{
    convW_body(W, K, N, Kpad, Npad, ldd, dst);
}

__global__ void convWg4_k(const float* __restrict__ W0, const float* __restrict__ W1,
                          const float* __restrict__ W2, const float* __restrict__ W3,
                          __half* __restrict__ dst)
{
    const float* W = (blockIdx.z == 0) ? W0 : (blockIdx.z == 1) ? W1
                   : (blockIdx.z == 2) ? W2 : W3;
    convW_body(W, DD, DD, KP1, DD, KP1, dst + (size_t)blockIdx.z * DD * KP1);
}

// ================= LayerNorm (eps = 2048), writes split-fp16 A directly =================
__global__ void ln_kernel(const float* __restrict__ seq,
                          const float* __restrict__ sc,
                          const float* __restrict__ bi)
{
    int b = blockIdx.x, t = threadIdx.x;
    const float* row = seq + ((size_t)b << 11);
    float v[8]; float s = 0.f, sq = 0.f;
#pragma unroll
    for (int q = 0; q < 8; q++) { v[q] = row[q*256 + t]; s += v[q]; sq = fmaf(v[q], v[q], sq); }
    __shared__ float sh_s[8], sh_q[8];
    __shared__ float s_mu, s_inv;
#pragma unroll
    for (int o = 16; o; o >>= 1) {
        s  += __shfl_down_sync(0xffffffffu, s,  o);
        sq += __shfl_down_sync(0xffffffffu, sq, o);
    }
    int warp = t >> 5, lane = t & 31;
    if (lane == 0) { sh_s[warp] = s; sh_q[warp] = sq; }
    __syncthreads();
    if (t == 0) {
        float ts = 0.f, tq = 0.f;
        for (int w = 0; w < 8; w++) { ts += sh_s[w]; tq += sh_q[w]; }
        float mu = ts / 2048.f;
        float var = tq / 2048.f - mu*mu;
        s_mu = mu; s_inv = rsqrtf(var + 2048.0f);
    }
    __syncthreads();
    float mu = s_mu, inv = s_inv;
    __half* arow = gA + (size_t)b * LDA1;
#pragma unroll
    for (int q = 0; q < 8; q++) {
        int col = q*256 + t;
        float x = (v[q] - mu) * inv * sc[col] + bi[col];
        __half hi, lo; split_h(x, hi, lo);
        arow[col] = hi; arow[KP1 + col] = lo;
    }
}

// ================= gating + block-diag recurrence =================
__global__ void gate_kernel(
    const float* __restrict__ b_i, const float* __restrict__ b_f,
    const float* __restrict__ b_z, const float* __restrict__ b_o,
    const float* __restrict__ Riw, const float* __restrict__ Rib,
    const float* __restrict__ Rfw, const float* __restrict__ Rfb,
    const float* __restrict__ Rzw, const float* __restrict__ Rzb,
    const float* __restrict__ Row_, const float* __restrict__ Rob,
    const float* __restrict__ c_tm1, const float* __restrict__ n_tm1,
    const float* __restrict__ h_tm1, const float* __restrict__ m_tm1,
    float* __restrict__ out, int write_states)
{
    size_t idx = (size_t)blockIdx.x * blockDim.x + threadIdx.x;
    if (idx >= (size_t)N_ELE) return;
    int b = (int)(idx >> 11);
    int j = (int)(idx & 2047);
    int h = j >> 7;
    int rem = j & 127;
    int n = rem >> 3;
    int e = rem & 7;

    const float* hp = h_tm1 + ((size_t)b << 11) + (h << 7) + (n << 3);
    float hv[8];
#pragma unroll
    for (int d = 0; d < 8; d++) hv[d] = hp[d];
    int sb = n*8 + e;
    int wb = n*64 + e;
    float bi_ = Rib[sb], bf_ = Rfb[sb], bz_ = Rzb[sb], bo_ = Rob[sb];
#pragma unroll
    for (int d = 0; d < 8; d++) {
        float hd = hv[d];
        bi_ = fmaf(hd, Riw[wb + d*8], bi_);
        bf_ = fmaf(hd, Rfw[wb + d*8], bf_);
        bz_ = fmaf(hd, Rzw[wb + d*8], bz_);
        bo_ = fmaf(hd, Row_[wb + d*8], bo_);
    }

    float it = g_gates[idx]                    + b_i[j] + bi_;
    float ft = g_gates[(size_t)N_ELE   + idx]  + b_f[j] + bf_;
    float zt = g_gates[(size_t)2*N_ELE + idx]  + b_z[j] + bz_;
    float ot = g_gates[(size_t)3*N_ELE + idx]  + b_o[j] + bo_;

    float mprev = m_tm1[idx];
    float mt = fmaxf(ft + mprev, it);
    float ie = expf(it - mt);
    float fe = expf(ft - mt + mprev);
    float z  = tanhf(zt);
    float ct = fe * c_tm1[idx] + ie * z;
    float nt = fe * n_tm1[idx] + ie;
    float o  = 1.f / (1.f + expf(-ot));
    float ht = o * (ct / nt);

    g_ht[idx] = ht;
    if (write_states) {
        out[(size_t)N_ELE   + idx] = ct;
        out[(size_t)2*N_ELE + idx] = nt;
        out[(size_t)3*N_ELE + idx] = ht;
        out[(size_t)4*N_ELE + idx] = mt;
    }
}

// ================= GroupNorm, writes split-fp16 A directly =================
__global__ void gn_kernel(const float* __restrict__ sc, const float* __restrict__ bi)
{
    int b = blockIdx.x, t = threadIdx.x;
    __shared__ float row[2048];
    __shared__ float ps[256], pq[256];
    __shared__ float gmu[16], gis[16];
    const float* hr = g_ht + ((size_t)b << 11);
#pragma unroll
    for (int q = 0; q < 8; q++) row[q*256 + t] = hr[q*256 + t];
    __syncthreads();

    int g = t >> 4, p = t & 15;
    float s = 0.f, sq = 0.f;
#pragma unroll
    for (int dg = 0; dg < 8; dg++) {
        float v = row[p*128 + g*8 + dg];
        s += v; sq = fmaf(v, v, sq);
    }
    ps[t] = s; pq[t] = sq;
    __syncthreads();
    for (int st = 8; st > 0; st >>= 1) {
        if (p < st) { ps[t] += ps[t + st]; pq[t] += pq[t + st]; }
        __syncthreads();
    }
    if (p == 0) {
        float mu = ps[t] / 128.f;
        float var = pq[t] / 128.f - mu*mu;
        gmu[g] = mu; gis[g] = rsqrtf(var + 1e-6f);
    }
    __syncthreads();
    __half* arow = gA + (size_t)b * LDA1;
#pragma unroll
    for (int q = 0; q < 8; q++) {
        int col = q*256 + t;
        int hd = col & 127;
        int gg = hd >> 3;
        float v = (row[col] - gmu[gg]) * gis[gg] * sc[hd] + bi[hd];
        __half hi, lo; split_h(v, hi, lo);
        arow[col] = hi; arow[KP1 + col] = lo;
    }
}

// ================= GLU, writes split-fp16 A (KP2 layout, zero-padded) =================
__global__ void glu_kernel()
{
    long idx = (long)blockIdx.x * blockDim.x + threadIdx.x;
    long tot = (long)BQ * KP2;
    if (idx >= tot) return;
    int b = (int)(idx / KP2);
    int j = (int)(idx % KP2);
    float r = 0.f;
    if (j < PROJ) {
        const float* up = g_gates + (long)b * UPN;
        float a = up[j];
        float x = up[j + PROJ];
        float x3 = x * x * x;
        float gg = 0.5f * x * (1.f + tanhf(0.7978845608028654f * (x + 0.044715f * x3)));
        r = a + gg;
    }
    __half hi, lo; split_h(r, hi, lo);
    __half* arow = gA + (long)b * LDA2;
    arow[j] = hi; arow[KP2 + j] = lo;
}

// ================= driver =================
extern "C" void kernel_launch(void* const* d_in, const int* in_sizes, int n_in,
                              void* d_out, int out_size)
{
    const float* seq      = (const float*)d_in[0];
    const float* c_tm1    = (const float*)d_in[1];
    const float* n_tm1    = (const float*)d_in[2];
    const float* h_tm1    = (const float*)d_in[3];
    const float* m_tm1    = (const float*)d_in[4];
    const float* ln_scale = (const float*)d_in[5];
    const float* ln_bias  = (const float*)d_in[6];
    const float* W_z      = (const float*)d_in[7];
    const float* b_z      = (const float*)d_in[8];
    const float* W_i      = (const float*)d_in[9];
    const float* b_i      = (const float*)d_in[10];
    const float* W_f      = (const float*)d_in[11];
    const float* b_f      = (const float*)d_in[12];
    const float* W_o      = (const float*)d_in[13];
    const float* b_o      = (const float*)d_in[14];
    const float* R_z_w    = (const float*)d_in[15];
    const float* R_z_b    = (const float*)d_in[16];
    const float* R_i_w    = (const float*)d_in[17];
    const float* R_i_b    = (const float*)d_in[18];
    const float* R_f_w    = (const float*)d_in[19];
    const float* R_f_b    = (const float*)d_in[20];
    const float* R_o_w    = (const float*)d_in[21];
    const float* R_o_b    = (const float*)d_in[22];
    const float* gn_scale = (const float*)d_in[23];
    const float* gn_bias  = (const float*)d_in[24];
    const float* up_w     = (const float*)d_in[25];
    const float* up_b     = (const float*)d_in[26];
    const float* down_w   = (const float*)d_in[27];
    const float* down_b   = (const float*)d_in[28];
    float* out = (float*)d_out;

    int write_states = (out_size >= 5 * N_ELE) ? 1 : 0;

    cudaFuncSetAttribute(mma_gemm, cudaFuncAttributeMaxDynamicSharedMemorySize, SMEMSZ);

    void *pA, *pBg, *pBu, *pBd, *pG;
    cudaGetSymbolAddress(&pA,  gA);
    cudaGetSymbolAddress(&pBg, gBg);
    cudaGetSymbolAddress(&pBu, gBu);
    cudaGetSymbolAddress(&pBd, gBd);
    cudaGetSymbolAddress(&pG,  g_gates);
    __half* A  = (__half*)pA;
    __half* Bg = (__half*)pBg;
    __half* Bu = (__half*)pBu;
    __half* Bd = (__half*)pBd;
    float* gates = (float*)pG;

    dim3 cw(32, 8);

    // conversions + LN (fused split)
    ln_kernel<<<BQ, 256>>>(seq, ln_scale, ln_bias);
    convWg4_k<<<dim3(KP1/32, DD/32, 4), cw>>>(W_i, W_f, W_z, W_o, Bg);
    convW_k<<<dim3(KP1/32, NPAD_UP/32), cw>>>(up_w,   DD,   UPN, KP1, NPAD_UP, KP1, Bu);
    convW_k<<<dim3(KP2/32, DD/32), cw>>>(down_w, PROJ, DD,  KP2, DD,      KP2, Bd);

    // four gate GEMMs (batched over z): slabs [i,f,z,o]
    mma_gemm<<<dim3(DD/BN, BQ/BM, 4), 256, SMEMSZ>>>(
        A, LDA1, Bg, KP1, gates, DD, DD, KP1,
        (long)DD*KP1, (long)N_ELE, nullptr, nullptr);

    // gating + recurrence + states
    gate_kernel<<<N_ELE/256, 256>>>(b_i, b_f, b_z, b_o,
                                    R_i_w, R_i_b, R_f_w, R_f_b,
                                    R_z_w, R_z_b, R_o_w, R_o_b,
                                    c_tm1, n_tm1, h_tm1, m_tm1,
                                    out, write_states);

    // GroupNorm -> split A
    gn_kernel<<<BQ, 256>>>(gn_scale, gn_bias);

    // up GEMM (+bias)
    mma_gemm<<<dim3((UPN + BN - 1)/BN, BQ/BM, 1), 256, SMEMSZ>>>(
        A, LDA1, Bu, KP1, gates, UPN, UPN, KP1, 0, 0, up_b, nullptr);

    // GLU -> split A (KP2 layout)
    glu_kernel<<<(unsigned)(((long)BQ*KP2 + 255)/256), 256>>>();

    // down GEMM (+bias +residual)
    mma_gemm<<<dim3(DD/BN, BQ/BM, 1), 256, SMEMSZ>>>(
        A, LDA2, Bd, KP2, out, DD, DD, KP2, 0, 0, down_b, seq);
}

// round 9
// speedup vs baseline: 3.5310x; 1.5004x over previous
#include <cuda_runtime.h>
#include <cuda_fp16.h>
#include <cstdint>
#include <math.h>

// ================= problem constants =================
#define BQ   4096
#define DD   2048
#define PROJ 2730
#define UPN  5460
#define N_ELE (BQ*DD)

// plain fp16 operands (single pass): error = a_lo*b + a*b_lo ~ 2^-11 rel, measured-safe
#define KP1   2048            // gates / up K
#define KP2   2752            // down K (2730 padded to mult of 64)
#define NPAD_UP 5632

// ================= scratch (static device globals) =================
__device__ __align__(256) __half gA [(size_t)BQ*KP2];
__device__ __align__(256) __half gBg[(size_t)4*DD*KP1];
__device__ __align__(256) __half gBu[(size_t)NPAD_UP*KP1];
__device__ __align__(256) __half gBd[(size_t)DD*KP2];
__device__ __align__(16) float g_gates[(size_t)4*N_ELE];   // gate preacts; reused for `up`
__device__ __align__(16) float g_ht[N_ELE];

// ================= PTX helpers =================
__device__ __forceinline__ uint32_t smem_u32(const void* p){
    uint32_t a; asm("{ .reg .u64 t; cvta.to.shared.u64 t, %1; cvt.u32.u64 %0, t; }" : "=r"(a) : "l"(p));
    return a;
}
#define CP16(s, g) asm volatile("cp.async.cg.shared.global [%0], [%1], 16;" :: "r"(s), "l"(g) : "memory")
#define CP_COMMIT() asm volatile("cp.async.commit_group;" ::: "memory")

#define LDSM_X4(r0,r1,r2,r3,addr) \
    asm volatile("ldmatrix.sync.aligned.m8n8.x4.shared.b16 {%0,%1,%2,%3}, [%4];" \
        : "=r"(r0), "=r"(r1), "=r"(r2), "=r"(r3) : "r"(addr))
#define MMA16816(d, a0,a1,a2,a3, b0,b1) \
    asm volatile("mma.sync.aligned.m16n8k16.row.col.f32.f16.f16.f32 " \
        "{%0,%1,%2,%3}, {%4,%5,%6,%7}, {%8,%9}, {%0,%1,%2,%3};" \
        : "+f"((d)[0]), "+f"((d)[1]), "+f"((d)[2]), "+f"((d)[3]) \
        : "r"(a0), "r"(a1), "r"(a2), "r"(a3), "r"(b0), "r"(b1))

// ================= HMMA GEMM: C[M,N] = A[M,K] * Bt[N,K]^T =================
// CTA tile 128x128x64, 8 warps (2m x 4n), warp tile 64x32, 3-stage cp.async,
// single barrier per chunk, 2 CTAs/SM. SMEM rows 128B, swizzle g' = g ^ (row&7).
#define BM 128
#define BN 128
#define BK 64
#define SB_OFF    16384u
#define STAGE_SZ  32768u
#define SMEMSZ    98304

__global__ void __launch_bounds__(256, 2) mma_gemm(
    const __half* __restrict__ A, long lda,
    const __half* __restrict__ B, long ldb,
    float* __restrict__ C, int N, int ldc, int Kp,
    long bStride, long cStride,
    const float* __restrict__ bias,
    const float* __restrict__ resid)
{
    extern __shared__ __align__(1024) char smem[];
    uint32_t base = smem_u32(smem);

    int tid  = threadIdx.x;
    int lane = tid & 31;
    int wid  = tid >> 5;
    int n0 = blockIdx.x * BN;
    int m0 = blockIdx.y * BM;
    B += (long)blockIdx.z * bStride;
    C += (long)blockIdx.z * cStride;

    // ---- loader slots: row = tid>>1 (0..127), 4 granules starting at (tid&1)*4
    int lr  = tid >> 1;
    int g0  = (tid & 1) * 4;
    const char* gAp = (const char*)(A + (long)(m0 + lr) * lda) + g0*16;
    const char* gBp = (const char*)(B + (long)(n0 + lr) * ldb) + g0*16;
    uint32_t aswz[4];
#pragma unroll
    for (int q = 0; q < 4; q++)
        aswz[q] = (uint32_t)((lr*8 + ((g0 + q) ^ (lr & 7))) * 16);

    // ---- warp tiling: 2(m) x 4(n), warp tile 64x32
    int warp_m = wid & 1;
    int warp_n = wid >> 1;

    int rAq[4];
#pragma unroll
    for (int mt = 0; mt < 4; mt++) rAq[mt] = warp_m*64 + mt*16 + (lane & 15);
    int cAoff = lane >> 4;
    int rBq[2];
#pragma unroll
    for (int np = 0; np < 2; np++) rBq[np] = warp_n*32 + np*16 + ((lane >> 4) << 3) + (lane & 7);
    int cBoff = (lane >> 3) & 1;

    float acc[4][4][4];
#pragma unroll
    for (int mt = 0; mt < 4; mt++)
#pragma unroll
        for (int nt = 0; nt < 4; nt++)
#pragma unroll
            for (int q = 0; q < 4; q++) acc[mt][nt][q] = 0.f;

    int NC = Kp / BK;

    // prologue: chunks 0,1 -> stages 0,1
#pragma unroll
    for (int s = 0; s < 2; s++) {
        uint32_t sb = base + s * STAGE_SZ;
        long ko = (long)s * 128;
#pragma unroll
        for (int q = 0; q < 4; q++) CP16(sb + aswz[q],          gAp + ko + q*16);
#pragma unroll
        for (int q = 0; q < 4; q++) CP16(sb + SB_OFF + aswz[q], gBp + ko + q*16);
        CP_COMMIT();
    }

    uint32_t stage_of[3] = { base, base + STAGE_SZ, base + 2*STAGE_SZ };
    int s_c = 0, s_nn = 2;

    for (int c = 0; c < NC; c++) {
        if (c + 1 < NC) asm volatile("cp.async.wait_group 1;" ::: "memory");
        else            asm volatile("cp.async.wait_group 0;" ::: "memory");
        __syncthreads();

        uint32_t sA = stage_of[s_c];
        uint32_t sB = sA + SB_OFF;

#pragma unroll
        for (int kk = 0; kk < 4; kk++) {
            uint32_t a[4][4], b[4][2];
            int cA = kk*2 + cAoff;
#pragma unroll
            for (int mt = 0; mt < 4; mt++) {
                int r = rAq[mt];
                uint32_t ad = sA + (uint32_t)((r*8 + (cA ^ (r & 7))) * 16);
                LDSM_X4(a[mt][0], a[mt][1], a[mt][2], a[mt][3], ad);
            }
            int cB = kk*2 + cBoff;
#pragma unroll
            for (int np = 0; np < 2; np++) {
                int r = rBq[np];
                uint32_t bd = sB + (uint32_t)((r*8 + (cB ^ (r & 7))) * 16);
                LDSM_X4(b[2*np][0], b[2*np][1], b[2*np+1][0], b[2*np+1][1], bd);
            }
#pragma unroll
            for (int mt = 0; mt < 4; mt++)
#pragma unroll
                for (int nt = 0; nt < 4; nt++)
                    MMA16816(acc[mt][nt], a[mt][0], a[mt][1], a[mt][2], a[mt][3],
                             b[nt][0], b[nt][1]);
        }

        if (c + 2 < NC) {
            uint32_t sb = stage_of[s_nn];
            long ko = (long)(c + 2) * 128;
#pragma unroll
            for (int q = 0; q < 4; q++) CP16(sb + aswz[q],          gAp + ko + q*16);
#pragma unroll
            for (int q = 0; q < 4; q++) CP16(sb + SB_OFF + aswz[q], gBp + ko + q*16);
            CP_COMMIT();
        }

        s_c  = (s_c  == 2) ? 0 : s_c  + 1;
        s_nn = (s_nn == 2) ? 0 : s_nn + 1;
    }

    // ---- epilogue
#pragma unroll
    for (int mt = 0; mt < 4; mt++) {
        int r0 = m0 + warp_m*64 + mt*16 + (lane >> 2);
        int r1 = r0 + 8;
        size_t o0 = (size_t)r0 * ldc;
        size_t o1 = (size_t)r1 * ldc;
#pragma unroll
        for (int nt = 0; nt < 4; nt++) {
            int col = n0 + warp_n*32 + nt*8 + (lane & 3)*2;
            if (col >= N) continue;
            float v0 = acc[mt][nt][0], v1 = acc[mt][nt][1];
            float v2 = acc[mt][nt][2], v3 = acc[mt][nt][3];
            if (bias)  { float b0 = bias[col], b1 = bias[col+1];
                         v0 += b0; v1 += b1; v2 += b0; v3 += b1; }
            if (resid) { const float2 q0 = *(const float2*)(resid + o0 + col);
                         const float2 q1 = *(const float2*)(resid + o1 + col);
                         v0 += q0.x; v1 += q0.y; v2 += q1.x; v3 += q1.y; }
            *(float2*)(C + o0 + col) = make_float2(v0, v1);
            *(float2*)(C + o1 + col) = make_float2(v2, v3);
        }
    }
}

// ================= weight conversion: W[K,N] -> Bt[Npad, Kpad] =================
__device__ __forceinline__ void convW_body(const float* W, int K, int N, int Kpad, int Npad,
                                           long ldd, __half* dst)
{
    __shared__ float t[32][33];
    int k0 = blockIdx.x * 32, nn0 = blockIdx.y * 32;
    int tx = threadIdx.x, ty = threadIdx.y;   // (32, 8)
#pragma unroll
    for (int i = ty; i < 32; i += 8) {
        int k = k0 + i, n = nn0 + tx;
        t[i][tx] = (k < K && n < N) ? W[(long)k * N + n] : 0.f;
    }
    __syncthreads();
#pragma unroll
    for (int i = ty; i < 32; i += 8) {
        int n = nn0 + i;
        if (n >= Npad) continue;
        int k = k0 + tx;
        dst[(long)n * ldd + k] = __float2half(t[tx][i]);
    }
}

__global__ void convW_k(const float* __restrict__ W, int K, int N, int Kpad, int Npad,
                        long ldd, __half* __restrict__ dst)
{
    convW_body(W, K, N, Kpad, Npad, ldd, dst);
}

__global__ void convWg4_k(const float* __restrict__ W0, const float* __restrict__ W1,
                          const float* __restrict__ W2, const float* __restrict__ W3,
                          __half* __restrict__ dst)
{
    const float* W = (blockIdx.z == 0) ? W0 : (blockIdx.z == 1) ? W1
                   : (blockIdx.z == 2) ? W2 : W3;
    convW_body(W, DD, DD, KP1, DD, KP1, dst + (size_t)blockIdx.z * DD * KP1);
}

// ================= LayerNorm (eps = 2048), writes fp16 A directly =================
__global__ void ln_kernel(const float* __restrict__ seq,
                          const float* __restrict__ sc,
                          const float* __restrict__ bi)
{
    int b = blockIdx.x, t = threadIdx.x;
    const float* row = seq + ((size_t)b << 11);
    float v[8]; float s = 0.f, sq = 0.f;
#pragma unroll
    for (int q = 0; q < 8; q++) { v[q] = row[q*256 + t]; s += v[q]; sq = fmaf(v[q], v[q], sq); }
    __shared__ float sh_s[8], sh_q[8];
    __shared__ float s_mu, s_inv;
#pragma unroll
    for (int o = 16; o; o >>= 1) {
        s  += __shfl_down_sync(0xffffffffu, s,  o);
        sq += __shfl_down_sync(0xffffffffu, sq, o);
    }
    int warp = t >> 5, lane = t & 31;
    if (lane == 0) { sh_s[warp] = s; sh_q[warp] = sq; }
    __syncthreads();
    if (t == 0) {
        float ts = 0.f, tq = 0.f;
        for (int w = 0; w < 8; w++) { ts += sh_s[w]; tq += sh_q[w]; }
        float mu = ts / 2048.f;
        float var = tq / 2048.f - mu*mu;
        s_mu = mu; s_inv = rsqrtf(var + 2048.0f);
    }
    __syncthreads();
    float mu = s_mu, inv = s_inv;
    __half* arow = gA + (size_t)b * KP1;
#pragma unroll
    for (int q = 0; q < 8; q++) {
        int col = q*256 + t;
        float x = (v[q] - mu) * inv * sc[col] + bi[col];
        arow[col] = __float2half(x);
    }
}

// ================= gating + block-diag recurrence =================
__global__ void gate_kernel(
    const float* __restrict__ b_i, const float* __restrict__ b_f,
    const float* __restrict__ b_z, const float* __restrict__ b_o,
    const float* __restrict__ Riw, const float* __restrict__ Rib,
    const float* __restrict__ Rfw, const float* __restrict__ Rfb,
    const float* __restrict__ Rzw, const float* __restrict__ Rzb,
    const float* __restrict__ Row_, const float* __restrict__ Rob,
    const float* __restrict__ c_tm1, const float* __restrict__ n_tm1,
    const float* __restrict__ h_tm1, const float* __restrict__ m_tm1,
    float* __restrict__ out, int write_states)
{
    size_t idx = (size_t)blockIdx.x * blockDim.x + threadIdx.x;
    if (idx >= (size_t)N_ELE) return;
    int b = (int)(idx >> 11);
    int j = (int)(idx & 2047);
    int h = j >> 7;
    int rem = j & 127;
    int n = rem >> 3;
    int e = rem & 7;

    const float* hp = h_tm1 + ((size_t)b << 11) + (h << 7) + (n << 3);
    float hv[8];
#pragma unroll
    for (int d = 0; d < 8; d++) hv[d] = hp[d];
    int sb = n*8 + e;
    int wb = n*64 + e;
    float bi_ = Rib[sb], bf_ = Rfb[sb], bz_ = Rzb[sb], bo_ = Rob[sb];
#pragma unroll
    for (int d = 0; d < 8; d++) {
        float hd = hv[d];
        bi_ = fmaf(hd, Riw[wb + d*8], bi_);
        bf_ = fmaf(hd, Rfw[wb + d*8], bf_);
        bz_ = fmaf(hd, Rzw[wb + d*8], bz_);
        bo_ = fmaf(hd, Row_[wb + d*8], bo_);
    }

    float it = g_gates[idx]                    + b_i[j] + bi_;
    float ft = g_gates[(size_t)N_ELE   + idx]  + b_f[j] + bf_;
    float zt = g_gates[(size_t)2*N_ELE + idx]  + b_z[j] + bz_;
    float ot = g_gates[(size_t)3*N_ELE + idx]  + b_o[j] + bo_;

    float mprev = m_tm1[idx];
    float mt = fmaxf(ft + mprev, it);
    float ie = expf(it - mt);
    float fe = expf(ft - mt + mprev);
    float z  = tanhf(zt);
    float ct = fe * c_tm1[idx] + ie * z;
    float nt = fe * n_tm1[idx] + ie;
    float o  = 1.f / (1.f + expf(-ot));
    float ht = o * (ct / nt);

    g_ht[idx] = ht;
    if (write_states) {
        out[(size_t)N_ELE   + idx] = ct;
        out[(size_t)2*N_ELE + idx] = nt;
        out[(size_t)3*N_ELE + idx] = ht;
        out[(size_t)4*N_ELE + idx] = mt;
    }
}

// ================= GroupNorm, writes fp16 A directly =================
__global__ void gn_kernel(const float* __restrict__ sc, const float* __restrict__ bi)
{
    int b = blockIdx.x, t = threadIdx.x;
    __shared__ float row[2048];
    __shared__ float ps[256], pq[256];
    __shared__ float gmu[16], gis[16];
    const float* hr = g_ht + ((size_t)b << 11);
#pragma unroll
    for (int q = 0; q < 8; q++) row[q*256 + t] = hr[q*256 + t];
    __syncthreads();

    int g = t >> 4, p = t & 15;
    float s = 0.f, sq = 0.f;
#pragma unroll
    for (int dg = 0; dg < 8; dg++) {
        float v = row[p*128 + g*8 + dg];
        s += v; sq = fmaf(v, v, sq);
    }
    ps[t] = s; pq[t] = sq;
    __syncthreads();
    for (int st = 8; st > 0; st >>= 1) {
        if (p < st) { ps[t] += ps[t + st]; pq[t] += pq[t + st]; }
        __syncthreads();
    }
    if (p == 0) {
        float mu = ps[t] / 128.f;
        float var = pq[t] / 128.f - mu*mu;
        gmu[g] = mu; gis[g] = rsqrtf(var + 1e-6f);
    }
    __syncthreads();
    __half* arow = gA + (size_t)b * KP1;
#pragma unroll
    for (int q = 0; q < 8; q++) {
        int col = q*256 + t;
        int hd = col & 127;
        int gg = hd >> 3;
        float v = (row[col] - gmu[gg]) * gis[gg] * sc[hd] + bi[hd];
        arow[col] = __float2half(v);
    }
}

// ================= GLU, writes fp16 A (KP2 layout, zero-padded) =================
__global__ void glu_kernel()
{
    long idx = (long)blockIdx.x * blockDim.x + threadIdx.x;
    long tot = (long)BQ * KP2;
    if (idx >= tot) return;
    int b = (int)(idx / KP2);
    int j = (int)(idx % KP2);
    float r = 0.f;
    if (j < PROJ) {
        const float* up = g_gates + (long)b * UPN;
        float a = up[j];
        float x = up[j + PROJ];
        float x3 = x * x * x;
        float gg = 0.5f * x * (1.f + tanhf(0.7978845608028654f * (x + 0.044715f * x3)));
        r = a + gg;
    }
    gA[(long)b * KP2 + j] = __float2half(r);
}

// ================= driver =================
extern "C" void kernel_launch(void* const* d_in, const int* in_sizes, int n_in,
                              void* d_out, int out_size)
{
    const float* seq      = (const float*)d_in[0];
    const float* c_tm1    = (const float*)d_in[1];
    const float* n_tm1    = (const float*)d_in[2];
    const float* h_tm1    = (const float*)d_in[3];
    const float* m_tm1    = (const float*)d_in[4];
    const float* ln_scale = (const float*)d_in[5];
    const float* ln_bias  = (const float*)d_in[6];
    const float* W_z      = (const float*)d_in[7];
    const float* b_z      = (const float*)d_in[8];
    const float* W_i      = (const float*)d_in[9];
    const float* b_i      = (const float*)d_in[10];
    const float* W_f      = (const float*)d_in[11];
    const float* b_f      = (const float*)d_in[12];
    const float* W_o      = (const float*)d_in[13];
    const float* b_o      = (const float*)d_in[14];
    const float* R_z_w    = (const float*)d_in[15];
    const float* R_z_b    = (const float*)d_in[16];
    const float* R_i_w    = (const float*)d_in[17];
    const float* R_i_b    = (const float*)d_in[18];
    const float* R_f_w    = (const float*)d_in[19];
    const float* R_f_b    = (const float*)d_in[20];
    const float* R_o_w    = (const float*)d_in[21];
    const float* R_o_b    = (const float*)d_in[22];
    const float* gn_scale = (const float*)d_in[23];
    const float* gn_bias  = (const float*)d_in[24];
    const float* up_w     = (const float*)d_in[25];
    const float* up_b     = (const float*)d_in[26];
    const float* down_w   = (const float*)d_in[27];
    const float* down_b   = (const float*)d_in[28];
    float* out = (float*)d_out;

    int write_states = (out_size >= 5 * N_ELE) ? 1 : 0;

    cudaFuncSetAttribute(mma_gemm, cudaFuncAttributeMaxDynamicSharedMemorySize, SMEMSZ);

    void *pA, *pBg, *pBu, *pBd, *pG;
    cudaGetSymbolAddress(&pA,  gA);
    cudaGetSymbolAddress(&pBg, gBg);
    cudaGetSymbolAddress(&pBu, gBu);
    cudaGetSymbolAddress(&pBd, gBd);
    cudaGetSymbolAddress(&pG,  g_gates);
    __half* A  = (__half*)pA;
    __half* Bg = (__half*)pBg;
    __half* Bu = (__half*)pBu;
    __half* Bd = (__half*)pBd;
    float* gates = (float*)pG;

    dim3 cw(32, 8);

    // conversions + LN (fp16 direct)
    ln_kernel<<<BQ, 256>>>(seq, ln_scale, ln_bias);
    convWg4_k<<<dim3(KP1/32, DD/32, 4), cw>>>(W_i, W_f, W_z, W_o, Bg);
    convW_k<<<dim3(KP1/32, NPAD_UP/32), cw>>>(up_w,   DD,   UPN, KP1, NPAD_UP, KP1, Bu);
    convW_k<<<dim3(KP2/32, DD/32), cw>>>(down_w, PROJ, DD,  KP2, DD,      KP2, Bd);

    // four gate GEMMs (batched over z): slabs [i,f,z,o]
    mma_gemm<<<dim3(DD/BN, BQ/BM, 4), 256, SMEMSZ>>>(
        A, KP1, Bg, KP1, gates, DD, DD, KP1,
        (long)DD*KP1, (long)N_ELE, nullptr, nullptr);

    // gating + recurrence + states
    gate_kernel<<<N_ELE/256, 256>>>(b_i, b_f, b_z, b_o,
                                    R_i_w, R_i_b, R_f_w, R_f_b,
                                    R_z_w, R_z_b, R_o_w, R_o_b,
                                    c_tm1, n_tm1, h_tm1, m_tm1,
                                    out, write_states);

    // GroupNorm -> fp16 A
    gn_kernel<<<BQ, 256>>>(gn_scale, gn_bias);

    // up GEMM (+bias)
    mma_gemm<<<dim3((UPN + BN - 1)/BN, BQ/BM, 1), 256, SMEMSZ>>>(
        A, KP1, Bu, KP1, gates, UPN, UPN, KP1, 0, 0, up_b, nullptr);

    // GLU -> fp16 A (KP2 layout)
    glu_kernel<<<(unsigned)(((long)BQ*KP2 + 255)/256), 256>>>();

    // down GEMM (+bias +residual)
    mma_gemm<<<dim3(DD/BN, BQ/BM, 1), 256, SMEMSZ>>>(
        A, KP2, Bd, KP2, out, DD, DD, KP2, 0, 0, down_b, seq);
}

// round 11
// speedup vs baseline: 3.8173x; 1.0811x over previous
#include <cuda_runtime.h>
#include <cuda_fp16.h>
#include <cstdint>
#include <math.h>

// ================= problem constants =================
#define BQ   4096
#define DD   2048
#define PROJ 2730
#define UPN  5460
#define N_ELE (BQ*DD)

#define KP1   2048            // gates / up K
#define KP2   2752            // down K (2730 padded to mult of 64)
#define NPAD_UP 5632

// ================= scratch (static device globals) =================
__device__ __align__(256) __half gA  [(size_t)BQ*KP1];   // LN / GN output (A operand)
__device__ __align__(256) __half gGlu[(size_t)BQ*KP2];   // GLU output (down-GEMM A) — separate buffer (R10 race fix)
__device__ __align__(256) __half gBg[(size_t)4*DD*KP1];
__device__ __align__(256) __half gBu[(size_t)NPAD_UP*KP1];
__device__ __align__(256) __half gBd[(size_t)DD*KP2];
__device__ __align__(16) float g_gates[(size_t)4*N_ELE];

// ================= PTX helpers =================
__device__ __forceinline__ uint32_t smem_u32(const void* p){
    uint32_t a; asm("{ .reg .u64 t; cvta.to.shared.u64 t, %1; cvt.u32.u64 %0, t; }" : "=r"(a) : "l"(p));
    return a;
}
#define CP16(s, g) asm volatile("cp.async.cg.shared.global [%0], [%1], 16;" :: "r"(s), "l"(g) : "memory")
#define CP_COMMIT() asm volatile("cp.async.commit_group;" ::: "memory")

#define LDSM_X4(r0,r1,r2,r3,addr) \
    asm volatile("ldmatrix.sync.aligned.m8n8.x4.shared.b16 {%0,%1,%2,%3}, [%4];" \
        : "=r"(r0), "=r"(r1), "=r"(r2), "=r"(r3) : "r"(addr))
#define MMA16816(d, a0,a1,a2,a3, b0,b1) \
    asm volatile("mma.sync.aligned.m16n8k16.row.col.f32.f16.f16.f32 " \
        "{%0,%1,%2,%3}, {%4,%5,%6,%7}, {%8,%9}, {%0,%1,%2,%3};" \
        : "+f"((d)[0]), "+f"((d)[1]), "+f"((d)[2]), "+f"((d)[3]) \
        : "r"(a0), "r"(a1), "r"(a2), "r"(a3), "r"(b0), "r"(b1))

__device__ __forceinline__ float gelu_t(float x){
    float x3 = x * x * x;
    return 0.5f * x * (1.f + tanhf(0.7978845608028654f * (x + 0.044715f * x3)));
}

// ================= HMMA GEMM (generic): C[M,N] = A[M,K] * Bt[N,K]^T =================
#define BM 128
#define BN 128
#define BK 64
#define SB_OFF    16384u
#define STAGE_SZ  32768u
#define SMEMSZ    98304

__global__ void __launch_bounds__(256, 2) mma_gemm(
    const __half* __restrict__ A, long lda,
    const __half* __restrict__ B, long ldb,
    float* __restrict__ C, int N, int ldc, int Kp,
    long bStride, long cStride,
    const float* __restrict__ bias,
    const float* __restrict__ resid)
{
    extern __shared__ __align__(1024) char smem[];
    uint32_t base = smem_u32(smem);

    int tid  = threadIdx.x;
    int lane = tid & 31;
    int wid  = tid >> 5;
    int n0 = blockIdx.x * BN;
    int m0 = blockIdx.y * BM;
    B += (long)blockIdx.z * bStride;
    C += (long)blockIdx.z * cStride;

    int lr  = tid >> 1;
    int g0  = (tid & 1) * 4;
    const char* gAp = (const char*)(A + (long)(m0 + lr) * lda) + g0*16;
    const char* gBp = (const char*)(B + (long)(n0 + lr) * ldb) + g0*16;
    uint32_t aswz[4];
#pragma unroll
    for (int q = 0; q < 4; q++)
        aswz[q] = (uint32_t)((lr*8 + ((g0 + q) ^ (lr & 7))) * 16);

    int warp_m = wid & 1;
    int warp_n = wid >> 1;

    int rAq[4];
#pragma unroll
    for (int mt = 0; mt < 4; mt++) rAq[mt] = warp_m*64 + mt*16 + (lane & 15);
    int cAoff = lane >> 4;
    int rBq[2];
#pragma unroll
    for (int np = 0; np < 2; np++) rBq[np] = warp_n*32 + np*16 + ((lane >> 4) << 3) + (lane & 7);
    int cBoff = (lane >> 3) & 1;

    float acc[4][4][4];
#pragma unroll
    for (int mt = 0; mt < 4; mt++)
#pragma unroll
        for (int nt = 0; nt < 4; nt++)
#pragma unroll
            for (int q = 0; q < 4; q++) acc[mt][nt][q] = 0.f;

    int NC = Kp / BK;

#pragma unroll
    for (int s = 0; s < 2; s++) {
        uint32_t sb = base + s * STAGE_SZ;
        long ko = (long)s * 128;
#pragma unroll
        for (int q = 0; q < 4; q++) CP16(sb + aswz[q],          gAp + ko + q*16);
#pragma unroll
        for (int q = 0; q < 4; q++) CP16(sb + SB_OFF + aswz[q], gBp + ko + q*16);
        CP_COMMIT();
    }

    uint32_t stage_of[3] = { base, base + STAGE_SZ, base + 2*STAGE_SZ };
    int s_c = 0, s_nn = 2;

    for (int c = 0; c < NC; c++) {
        if (c + 1 < NC) asm volatile("cp.async.wait_group 1;" ::: "memory");
        else            asm volatile("cp.async.wait_group 0;" ::: "memory");
        __syncthreads();

        uint32_t sA = stage_of[s_c];
        uint32_t sB = sA + SB_OFF;

#pragma unroll
        for (int kk = 0; kk < 4; kk++) {
            uint32_t a[4][4], b[4][2];
            int cA = kk*2 + cAoff;
#pragma unroll
            for (int mt = 0; mt < 4; mt++) {
                int r = rAq[mt];
                uint32_t ad = sA + (uint32_t)((r*8 + (cA ^ (r & 7))) * 16);
                LDSM_X4(a[mt][0], a[mt][1], a[mt][2], a[mt][3], ad);
            }
            int cB = kk*2 + cBoff;
#pragma unroll
            for (int np = 0; np < 2; np++) {
                int r = rBq[np];
                uint32_t bd = sB + (uint32_t)((r*8 + (cB ^ (r & 7))) * 16);
                LDSM_X4(b[2*np][0], b[2*np][1], b[2*np+1][0], b[2*np+1][1], bd);
            }
#pragma unroll
            for (int mt = 0; mt < 4; mt++)
#pragma unroll
                for (int nt = 0; nt < 4; nt++)
                    MMA16816(acc[mt][nt], a[mt][0], a[mt][1], a[mt][2], a[mt][3],
                             b[nt][0], b[nt][1]);
        }

        if (c + 2 < NC) {
            uint32_t sb = stage_of[s_nn];
            long ko = (long)(c + 2) * 128;
#pragma unroll
            for (int q = 0; q < 4; q++) CP16(sb + aswz[q],          gAp + ko + q*16);
#pragma unroll
            for (int q = 0; q < 4; q++) CP16(sb + SB_OFF + aswz[q], gBp + ko + q*16);
            CP_COMMIT();
        }

        s_c  = (s_c  == 2) ? 0 : s_c  + 1;
        s_nn = (s_nn == 2) ? 0 : s_nn + 1;
    }

#pragma unroll
    for (int mt = 0; mt < 4; mt++) {
        int r0 = m0 + warp_m*64 + mt*16 + (lane >> 2);
        int r1 = r0 + 8;
        size_t o0 = (size_t)r0 * ldc;
        size_t o1 = (size_t)r1 * ldc;
#pragma unroll
        for (int nt = 0; nt < 4; nt++) {
            int col = n0 + warp_n*32 + nt*8 + (lane & 3)*2;
            if (col >= N) continue;
            float v0 = acc[mt][nt][0], v1 = acc[mt][nt][1];
            float v2 = acc[mt][nt][2], v3 = acc[mt][nt][3];
            if (bias)  { float b0 = bias[col], b1 = bias[col+1];
                         v0 += b0; v1 += b1; v2 += b0; v3 += b1; }
            if (resid) { const float2 q0 = *(const float2*)(resid + o0 + col);
                         const float2 q1 = *(const float2*)(resid + o1 + col);
                         v0 += q0.x; v1 += q0.y; v2 += q1.x; v3 += q1.y; }
            *(float2*)(C + o0 + col) = make_float2(v0, v1);
            *(float2*)(C + o1 + col) = make_float2(v2, v3);
        }
    }
}

// ================= fused up-GEMM + GLU: gGlu[m, j] = fp16(up1 + gelu(up2)) =================
// CTA tile 128m x 64j, TWO halves (B rows j and j+PROJ) sharing the A tile.
// Reads gA (stride KP1), writes gGlu (stride KP2) — DISJOINT buffers.
__global__ void __launch_bounds__(256, 2) mma_gemm_glu(
    const __half* __restrict__ A,
    const __half* __restrict__ Bu,
    const float* __restrict__ up_b)
{
    extern __shared__ __align__(1024) char smem[];
    uint32_t base = smem_u32(smem);

    int tid  = threadIdx.x;
    int lane = tid & 31;
    int wid  = tid >> 5;
    int j0 = blockIdx.x * 64;
    int m0 = blockIdx.y * BM;

    int lrA = tid >> 1;
    int gA0 = (tid & 1) * 4;
    const char* pA = (const char*)(A + (long)(m0 + lrA) * KP1) + gA0*16;
    uint32_t aswz[4];
#pragma unroll
    for (int q = 0; q < 4; q++)
        aswz[q] = (uint32_t)((lrA*8 + ((gA0 + q) ^ (lrA & 7))) * 16);

    int lrB = tid >> 2;
    int gB0 = tid & 3;
    const char* pB1 = (const char*)(Bu + (long)(j0 + lrB) * KP1) + gB0*16;
    const char* pB2 = (const char*)(Bu + (long)(j0 + lrB + PROJ) * KP1) + gB0*16;
    uint32_t bswz[2];
    bswz[0] = (uint32_t)((lrB*8 + ((gB0    ) ^ (lrB & 7))) * 16);
    bswz[1] = (uint32_t)((lrB*8 + ((gB0 + 4) ^ (lrB & 7))) * 16);

    int warp_m = wid & 1;
    int warp_n = wid >> 1;

    int rAq[4];
#pragma unroll
    for (int mt = 0; mt < 4; mt++) rAq[mt] = warp_m*64 + mt*16 + (lane & 15);
    int cAoff = lane >> 4;
    int rB = warp_n*16 + ((lane >> 4) << 3) + (lane & 7);
    int cBoff = (lane >> 3) & 1;

    float acc[2][4][2][4];
#pragma unroll
    for (int h = 0; h < 2; h++)
#pragma unroll
        for (int mt = 0; mt < 4; mt++)
#pragma unroll
            for (int nt = 0; nt < 2; nt++)
#pragma unroll
                for (int q = 0; q < 4; q++) acc[h][mt][nt][q] = 0.f;

    const uint32_t B1_OFF = 16384u, B2_OFF = 24576u;
    const uint32_t STG = 32768u;
    int NC = KP1 / BK;

#pragma unroll
    for (int s = 0; s < 2; s++) {
        uint32_t sb = base + s * STG;
        long ko = (long)s * 128;
#pragma unroll
        for (int q = 0; q < 4; q++) CP16(sb + aswz[q], pA + ko + q*16);
        CP16(sb + B1_OFF + bswz[0], pB1 + ko);
        CP16(sb + B1_OFF + bswz[1], pB1 + ko + 64);
        CP16(sb + B2_OFF + bswz[0], pB2 + ko);
        CP16(sb + B2_OFF + bswz[1], pB2 + ko + 64);
        CP_COMMIT();
    }

    uint32_t stage_of[3] = { base, base + STG, base + 2*STG };
    int s_c = 0, s_nn = 2;

    for (int c = 0; c < NC; c++) {
        if (c + 1 < NC) asm volatile("cp.async.wait_group 1;" ::: "memory");
        else            asm volatile("cp.async.wait_group 0;" ::: "memory");
        __syncthreads();

        uint32_t sA = stage_of[s_c];

#pragma unroll
        for (int kk = 0; kk < 4; kk++) {
            uint32_t a[4][4], b1[2][2], b2[2][2];
            int cA = kk*2 + cAoff;
#pragma unroll
            for (int mt = 0; mt < 4; mt++) {
                int r = rAq[mt];
                uint32_t ad = sA + (uint32_t)((r*8 + (cA ^ (r & 7))) * 16);
                LDSM_X4(a[mt][0], a[mt][1], a[mt][2], a[mt][3], ad);
            }
            int cB = kk*2 + cBoff;
            uint32_t boff = (uint32_t)((rB*8 + (cB ^ (rB & 7))) * 16);
            LDSM_X4(b1[0][0], b1[0][1], b1[1][0], b1[1][1], sA + B1_OFF + boff);
            LDSM_X4(b2[0][0], b2[0][1], b2[1][0], b2[1][1], sA + B2_OFF + boff);
#pragma unroll
            for (int mt = 0; mt < 4; mt++)
#pragma unroll
                for (int nt = 0; nt < 2; nt++) {
                    MMA16816(acc[0][mt][nt], a[mt][0], a[mt][1], a[mt][2], a[mt][3],
                             b1[nt][0], b1[nt][1]);
                    MMA16816(acc[1][mt][nt], a[mt][0], a[mt][1], a[mt][2], a[mt][3],
                             b2[nt][0], b2[nt][1]);
                }
        }

        if (c + 2 < NC) {
            uint32_t sb = stage_of[s_nn];
            long ko = (long)(c + 2) * 128;
#pragma unroll
            for (int q = 0; q < 4; q++) CP16(sb + aswz[q], pA + ko + q*16);
            CP16(sb + B1_OFF + bswz[0], pB1 + ko);
            CP16(sb + B1_OFF + bswz[1], pB1 + ko + 64);
            CP16(sb + B2_OFF + bswz[0], pB2 + ko);
            CP16(sb + B2_OFF + bswz[1], pB2 + ko + 64);
            CP_COMMIT();
        }

        s_c  = (s_c  == 2) ? 0 : s_c  + 1;
        s_nn = (s_nn == 2) ? 0 : s_nn + 1;
    }

    // ---- fused GLU epilogue -> fp16 gGlu (zeros in KP2 padding columns)
#pragma unroll
    for (int mt = 0; mt < 4; mt++) {
        int r0 = m0 + warp_m*64 + mt*16 + (lane >> 2);
        int r1 = r0 + 8;
#pragma unroll
        for (int nt = 0; nt < 2; nt++) {
            int col = j0 + warp_n*16 + nt*8 + (lane & 3)*2;
            float o0 = 0.f, o1 = 0.f, o2 = 0.f, o3 = 0.f;
            if (col < PROJ) {
                float b1v = up_b[col], b1w = up_b[col+1];
                float b2v = up_b[col + PROJ], b2w = up_b[col+1 + PROJ];
                o0 = acc[0][mt][nt][0] + b1v + gelu_t(acc[1][mt][nt][0] + b2v);
                o1 = acc[0][mt][nt][1] + b1w + gelu_t(acc[1][mt][nt][1] + b2w);
                o2 = acc[0][mt][nt][2] + b1v + gelu_t(acc[1][mt][nt][2] + b2v);
                o3 = acc[0][mt][nt][3] + b1w + gelu_t(acc[1][mt][nt][3] + b2w);
            }
            __half2 h01 = __floats2half2_rn(o0, o1);
            __half2 h23 = __floats2half2_rn(o2, o3);
            *(__half2*)(gGlu + (size_t)r0 * KP2 + col) = h01;
            *(__half2*)(gGlu + (size_t)r1 * KP2 + col) = h23;
        }
    }
}

// ================= weight conversion: W[K,N] -> Bt[Npad, Kpad] =================
__device__ __forceinline__ void convW_body(const float* W, int K, int N, int Kpad, int Npad,
                                           long ldd, __half* dst)
{
    __shared__ float t[32][33];
    int k0 = blockIdx.x * 32, nn0 = blockIdx.y * 32;
    int tx = threadIdx.x, ty = threadIdx.y;
#pragma unroll
    for (int i = ty; i < 32; i += 8) {
        int k = k0 + i, n = nn0 + tx;
        t[i][tx] = (k < K && n < N) ? W[(long)k * N + n] : 0.f;
    }
    __syncthreads();
#pragma unroll
    for (int i = ty; i < 32; i += 8) {
        int n = nn0 + i;
        if (n >= Npad) continue;
        int k = k0 + tx;
        dst[(long)n * ldd + k] = __float2half(t[tx][i]);
    }
}

__global__ void convW_k(const float* __restrict__ W, int K, int N, int Kpad, int Npad,
                        long ldd, __half* __restrict__ dst)
{
    convW_body(W, K, N, Kpad, Npad, ldd, dst);
}

__global__ void convWg2_k(const float* __restrict__ W0, const float* __restrict__ W1,
                          __half* __restrict__ dst)
{
    const float* W = (blockIdx.z == 0) ? W0 : W1;
    convW_body(W, DD, DD, KP1, DD, KP1, dst + (size_t)blockIdx.z * DD * KP1);
}

// ================= LayerNorm (eps = 2048), writes fp16 gA =================
__global__ void ln_kernel(const float* __restrict__ seq,
                          const float* __restrict__ sc,
                          const float* __restrict__ bi)
{
    int b = blockIdx.x, t = threadIdx.x;
    const float* row = seq + ((size_t)b << 11);
    float v[8]; float s = 0.f, sq = 0.f;
#pragma unroll
    for (int q = 0; q < 8; q++) { v[q] = row[q*256 + t]; s += v[q]; sq = fmaf(v[q], v[q], sq); }
    __shared__ float sh_s[8], sh_q[8];
    __shared__ float s_mu, s_inv;
#pragma unroll
    for (int o = 16; o; o >>= 1) {
        s  += __shfl_down_sync(0xffffffffu, s,  o);
        sq += __shfl_down_sync(0xffffffffu, sq, o);
    }
    int warp = t >> 5, lane = t & 31;
    if (lane == 0) { sh_s[warp] = s; sh_q[warp] = sq; }
    __syncthreads();
    if (t == 0) {
        float ts = 0.f, tq = 0.f;
        for (int w = 0; w < 8; w++) { ts += sh_s[w]; tq += sh_q[w]; }
        float mu = ts / 2048.f;
        float var = tq / 2048.f - mu*mu;
        s_mu = mu; s_inv = rsqrtf(var + 2048.0f);
    }
    __syncthreads();
    float mu = s_mu, inv = s_inv;
    __half* arow = gA + (size_t)b * KP1;
#pragma unroll
    for (int q = 0; q < 8; q++) {
        int col = q*256 + t;
        float x = (v[q] - mu) * inv * sc[col] + bi[col];
        arow[col] = __float2half(x);
    }
}

// ================= fused gating + recurrence + states + GroupNorm -> fp16 gA =================
__global__ void gate_gn_kernel(
    const float* __restrict__ b_i, const float* __restrict__ b_f,
    const float* __restrict__ b_z, const float* __restrict__ b_o,
    const float* __restrict__ Riw, const float* __restrict__ Rib,
    const float* __restrict__ Rfw, const float* __restrict__ Rfb,
    const float* __restrict__ Rzw, const float* __restrict__ Rzb,
    const float* __restrict__ Row_, const float* __restrict__ Rob,
    const float* __restrict__ c_tm1, const float* __restrict__ n_tm1,
    const float* __restrict__ h_tm1, const float* __restrict__ m_tm1,
    const float* __restrict__ gn_sc, const float* __restrict__ gn_bi,
    float* __restrict__ out, int write_states)
{
    int b = blockIdx.x, t = threadIdx.x;
    __shared__ float hrow[2048];
    __shared__ float htrow[2048];
    __shared__ float ps[256], pq[256];
    __shared__ float gmu[16], gis[16];

    size_t boff = (size_t)b << 11;
#pragma unroll
    for (int q = 0; q < 8; q++) hrow[q*256 + t] = h_tm1[boff + q*256 + t];
    __syncthreads();

    float htv[8];
#pragma unroll
    for (int q = 0; q < 8; q++) {
        int j = q*256 + t;
        size_t idx = boff + j;
        int rem = j & 127;
        int n = rem >> 3;
        int e = rem & 7;
        int jb = j & ~7;
        int sb = n*8 + e;
        int wb = n*64 + e;
        float bi_ = Rib[sb], bf_ = Rfb[sb], bz_ = Rzb[sb], bo_ = Rob[sb];
#pragma unroll
        for (int d = 0; d < 8; d++) {
            float hd = hrow[jb + d];
            bi_ = fmaf(hd, Riw[wb + d*8], bi_);
            bf_ = fmaf(hd, Rfw[wb + d*8], bf_);
            bz_ = fmaf(hd, Rzw[wb + d*8], bz_);
            bo_ = fmaf(hd, Row_[wb + d*8], bo_);
        }
        float it = g_gates[idx]                   + b_i[j] + bi_;
        float ft = g_gates[(size_t)N_ELE   + idx] + b_f[j] + bf_;
        float zt = g_gates[(size_t)2*N_ELE + idx] + b_z[j] + bz_;
        float ot = g_gates[(size_t)3*N_ELE + idx] + b_o[j] + bo_;

        float mprev = m_tm1[idx];
        float mt = fmaxf(ft + mprev, it);
        float ie = expf(it - mt);
        float fe = expf(ft - mt + mprev);
        float z  = tanhf(zt);
        float ct = fe * c_tm1[idx] + ie * z;
        float nt = fe * n_tm1[idx] + ie;
        float o  = 1.f / (1.f + expf(-ot));
        float ht = o * (ct / nt);
        htv[q] = ht;
        if (write_states) {
            out[(size_t)N_ELE   + idx] = ct;
            out[(size_t)2*N_ELE + idx] = nt;
            out[(size_t)3*N_ELE + idx] = ht;
            out[(size_t)4*N_ELE + idx] = mt;
        }
    }
#pragma unroll
    for (int q = 0; q < 8; q++) htrow[q*256 + t] = htv[q];
    __syncthreads();

    int g = t >> 4, p = t & 15;
    float s = 0.f, sq = 0.f;
#pragma unroll
    for (int dg = 0; dg < 8; dg++) {
        float v = htrow[p*128 + g*8 + dg];
        s += v; sq = fmaf(v, v, sq);
    }
    ps[t] = s; pq[t] = sq;
    __syncthreads();
    for (int st = 8; st > 0; st >>= 1) {
        if (p < st) { ps[t] += ps[t + st]; pq[t] += pq[t + st]; }
        __syncthreads();
    }
    if (p == 0) {
        float mu = ps[t] / 128.f;
        float var = pq[t] / 128.f - mu*mu;
        gmu[g] = mu; gis[g] = rsqrtf(var + 1e-6f);
    }
    __syncthreads();
    __half* arow = gA + (size_t)b * KP1;
#pragma unroll
    for (int q = 0; q < 8; q++) {
        int col = q*256 + t;
        int hd = col & 127;
        int gg = hd >> 3;
        float v = (htrow[col] - gmu[gg]) * gis[gg] * gn_sc[hd] + gn_bi[hd];
        arow[col] = __float2half(v);
    }
}

// ================= driver =================
extern "C" void kernel_launch(void* const* d_in, const int* in_sizes, int n_in,
                              void* d_out, int out_size)
{
    const float* seq      = (const float*)d_in[0];
    const float* c_tm1    = (const float*)d_in[1];
    const float* n_tm1    = (const float*)d_in[2];
    const float* h_tm1    = (const float*)d_in[3];
    const float* m_tm1    = (const float*)d_in[4];
    const float* ln_scale = (const float*)d_in[5];
    const float* ln_bias  = (const float*)d_in[6];
    const float* W_z      = (const float*)d_in[7];
    const float* b_z      = (const float*)d_in[8];
    const float* W_i      = (const float*)d_in[9];
    const float* b_i      = (const float*)d_in[10];
    const float* W_f      = (const float*)d_in[11];
    const float* b_f      = (const float*)d_in[12];
    const float* W_o      = (const float*)d_in[13];
    const float* b_o      = (const float*)d_in[14];
    const float* R_z_w    = (const float*)d_in[15];
    const float* R_z_b    = (const float*)d_in[16];
    const float* R_i_w    = (const float*)d_in[17];
    const float* R_i_b    = (const float*)d_in[18];
    const float* R_f_w    = (const float*)d_in[19];
    const float* R_f_b    = (const float*)d_in[20];
    const float* R_o_w    = (const float*)d_in[21];
    const float* R_o_b    = (const float*)d_in[22];
    const float* gn_scale = (const float*)d_in[23];
    const float* gn_bias  = (const float*)d_in[24];
    const float* up_w     = (const float*)d_in[25];
    const float* up_b     = (const float*)d_in[26];
    const float* down_w   = (const float*)d_in[27];
    const float* down_b   = (const float*)d_in[28];
    float* out = (float*)d_out;

    int write_states = (out_size >= 5 * N_ELE) ? 1 : 0;

    cudaFuncSetAttribute(mma_gemm,     cudaFuncAttributeMaxDynamicSharedMemorySize, SMEMSZ);
    cudaFuncSetAttribute(mma_gemm_glu, cudaFuncAttributeMaxDynamicSharedMemorySize, SMEMSZ);

    void *pA, *pGlu, *pBg, *pBu, *pBd, *pG;
    cudaGetSymbolAddress(&pA,   gA);
    cudaGetSymbolAddress(&pGlu, gGlu);
    cudaGetSymbolAddress(&pBg,  gBg);
    cudaGetSymbolAddress(&pBu,  gBu);
    cudaGetSymbolAddress(&pBd,  gBd);
    cudaGetSymbolAddress(&pG,   g_gates);
    __half* A    = (__half*)pA;
    __half* Glu  = (__half*)pGlu;
    __half* Bg   = (__half*)pBg;
    __half* Bu   = (__half*)pBu;
    __half* Bd   = (__half*)pBd;
    float* gates = (float*)pG;

    dim3 cw(32, 8);

    // launches #1-#5 (ncu -s 5 -c 1 profiles the gate GEMM at #6)
    ln_kernel<<<BQ, 256>>>(seq, ln_scale, ln_bias);                                   // 1
    convWg2_k<<<dim3(KP1/32, DD/32, 2), cw>>>(W_i, W_f, Bg);                          // 2
    convWg2_k<<<dim3(KP1/32, DD/32, 2), cw>>>(W_z, W_o, Bg + 2L*DD*KP1);              // 3
    convW_k<<<dim3(KP1/32, NPAD_UP/32), cw>>>(up_w, DD, UPN, KP1, NPAD_UP, KP1, Bu);  // 4
    convW_k<<<dim3(KP2/32, DD/32), cw>>>(down_w, PROJ, DD, KP2, DD, KP2, Bd);         // 5

    // 6: four gate GEMMs (batched over z)
    mma_gemm<<<dim3(DD/BN, BQ/BM, 4), 256, SMEMSZ>>>(
        A, KP1, Bg, KP1, gates, DD, DD, KP1,
        (long)DD*KP1, (long)N_ELE, nullptr, nullptr);

    // 7: fused gating + recurrence + states + GroupNorm -> fp16 gA
    gate_gn_kernel<<<BQ, 256>>>(b_i, b_f, b_z, b_o,
                                R_i_w, R_i_b, R_f_w, R_f_b,
                                R_z_w, R_z_b, R_o_w, R_o_b,
                                c_tm1, n_tm1, h_tm1, m_tm1,
                                gn_scale, gn_bias,
                                out, write_states);

    // 8: fused up GEMM + GLU -> fp16 gGlu (disjoint from gA: no aliasing)
    mma_gemm_glu<<<dim3(KP2/64, BQ/BM), 256, SMEMSZ>>>(A, Bu, up_b);

    // 9: down GEMM (+bias +residual), reads gGlu
    mma_gemm<<<dim3(DD/BN, BQ/BM, 1), 256, SMEMSZ>>>(
        Glu, KP2, Bd, KP2, out, DD, DD, KP2, 0, 0, down_b, seq);
}

// round 12
// speedup vs baseline: 3.8177x; 1.0001x over previous
#include <cuda_runtime.h>
#include <cuda_fp16.h>
#include <cstdint>
#include <math.h>

// ================= problem constants =================
#define BQ   4096
#define DD   2048
#define PROJ 2730
#define UPN  5460
#define N_ELE (BQ*DD)

#define KP1   2048            // gates / up K
#define KP2   2752            // down K (2730 padded to mult of 64)
#define NPAD_UP 5632

// ================= scratch (static device globals) =================
__device__ __align__(256) __half gA  [(size_t)BQ*KP1];   // LN / GN output (A operand)
__device__ __align__(256) __half gGlu[(size_t)BQ*KP2];   // GLU output (down-GEMM A)
__device__ __align__(256) __half gBg[(size_t)4*DD*KP1];
__device__ __align__(256) __half gBu[(size_t)NPAD_UP*KP1];
__device__ __align__(256) __half gBd[(size_t)DD*KP2];
__device__ __align__(16) __half g_gates[(size_t)4*N_ELE];   // fp16 gate preacts

// ================= PTX helpers =================
__device__ __forceinline__ uint32_t smem_u32(const void* p){
    uint32_t a; asm("{ .reg .u64 t; cvta.to.shared.u64 t, %1; cvt.u32.u64 %0, t; }" : "=r"(a) : "l"(p));
    return a;
}
#define CP16(s, g) asm volatile("cp.async.cg.shared.global [%0], [%1], 16;" :: "r"(s), "l"(g) : "memory")
#define CP_COMMIT() asm volatile("cp.async.commit_group;" ::: "memory")

#define LDSM_X4(r0,r1,r2,r3,addr) \
    asm volatile("ldmatrix.sync.aligned.m8n8.x4.shared.b16 {%0,%1,%2,%3}, [%4];" \
        : "=r"(r0), "=r"(r1), "=r"(r2), "=r"(r3) : "r"(addr))
#define MMA16816(d, a0,a1,a2,a3, b0,b1) \
    asm volatile("mma.sync.aligned.m16n8k16.row.col.f32.f16.f16.f32 " \
        "{%0,%1,%2,%3}, {%4,%5,%6,%7}, {%8,%9}, {%0,%1,%2,%3};" \
        : "+f"((d)[0]), "+f"((d)[1]), "+f"((d)[2]), "+f"((d)[3]) \
        : "r"(a0), "r"(a1), "r"(a2), "r"(a3), "r"(b0), "r"(b1))

__device__ __forceinline__ float gelu_t(float x){
    float x3 = x * x * x;
    return 0.5f * x * (1.f + tanhf(0.7978845608028654f * (x + 0.044715f * x3)));
}

// ================= HMMA GEMM: C[M,N] = A[M,K] * Bt[N,K]^T =================
// HALF_OUT=true: C is __half (no bias/resid). false: fp32 C (+bias +resid).
#define BM 128
#define BN 128
#define BK 64
#define SB_OFF    16384u
#define STAGE_SZ  32768u
#define SMEMSZ    98304

template<bool HALF_OUT>
__global__ void __launch_bounds__(256, 2) mma_gemm(
    const __half* __restrict__ A, long lda,
    const __half* __restrict__ B, long ldb,
    void* __restrict__ Cv, int N, int ldc, int Kp,
    long bStride, long cStride,
    const float* __restrict__ bias,
    const float* __restrict__ resid)
{
    extern __shared__ __align__(1024) char smem[];
    uint32_t base = smem_u32(smem);

    int tid  = threadIdx.x;
    int lane = tid & 31;
    int wid  = tid >> 5;
    int n0 = blockIdx.x * BN;
    int m0 = blockIdx.y * BM;
    B += (long)blockIdx.z * bStride;

    int lr  = tid >> 1;
    int g0  = (tid & 1) * 4;
    const char* gAp = (const char*)(A + (long)(m0 + lr) * lda) + g0*16;
    const char* gBp = (const char*)(B + (long)(n0 + lr) * ldb) + g0*16;
    uint32_t aswz[4];
#pragma unroll
    for (int q = 0; q < 4; q++)
        aswz[q] = (uint32_t)((lr*8 + ((g0 + q) ^ (lr & 7))) * 16);

    int warp_m = wid & 1;
    int warp_n = wid >> 1;

    int rAq[4];
#pragma unroll
    for (int mt = 0; mt < 4; mt++) rAq[mt] = warp_m*64 + mt*16 + (lane & 15);
    int cAoff = lane >> 4;
    int rBq[2];
#pragma unroll
    for (int np = 0; np < 2; np++) rBq[np] = warp_n*32 + np*16 + ((lane >> 4) << 3) + (lane & 7);
    int cBoff = (lane >> 3) & 1;

    float acc[4][4][4];
#pragma unroll
    for (int mt = 0; mt < 4; mt++)
#pragma unroll
        for (int nt = 0; nt < 4; nt++)
#pragma unroll
            for (int q = 0; q < 4; q++) acc[mt][nt][q] = 0.f;

    int NC = Kp / BK;

#pragma unroll
    for (int s = 0; s < 2; s++) {
        uint32_t sb = base + s * STAGE_SZ;
        long ko = (long)s * 128;
#pragma unroll
        for (int q = 0; q < 4; q++) CP16(sb + aswz[q],          gAp + ko + q*16);
#pragma unroll
        for (int q = 0; q < 4; q++) CP16(sb + SB_OFF + aswz[q], gBp + ko + q*16);
        CP_COMMIT();
    }

    uint32_t stage_of[3] = { base, base + STAGE_SZ, base + 2*STAGE_SZ };
    int s_c = 0, s_nn = 2;

    for (int c = 0; c < NC; c++) {
        if (c + 1 < NC) asm volatile("cp.async.wait_group 1;" ::: "memory");
        else            asm volatile("cp.async.wait_group 0;" ::: "memory");
        __syncthreads();

        uint32_t sA = stage_of[s_c];
        uint32_t sB = sA + SB_OFF;

#pragma unroll
        for (int kk = 0; kk < 4; kk++) {
            uint32_t a[4][4], b[4][2];
            int cA = kk*2 + cAoff;
#pragma unroll
            for (int mt = 0; mt < 4; mt++) {
                int r = rAq[mt];
                uint32_t ad = sA + (uint32_t)((r*8 + (cA ^ (r & 7))) * 16);
                LDSM_X4(a[mt][0], a[mt][1], a[mt][2], a[mt][3], ad);
            }
            int cB = kk*2 + cBoff;
#pragma unroll
            for (int np = 0; np < 2; np++) {
                int r = rBq[np];
                uint32_t bd = sB + (uint32_t)((r*8 + (cB ^ (r & 7))) * 16);
                LDSM_X4(b[2*np][0], b[2*np][1], b[2*np+1][0], b[2*np+1][1], bd);
            }
#pragma unroll
            for (int mt = 0; mt < 4; mt++)
#pragma unroll
                for (int nt = 0; nt < 4; nt++)
                    MMA16816(acc[mt][nt], a[mt][0], a[mt][1], a[mt][2], a[mt][3],
                             b[nt][0], b[nt][1]);
        }

        if (c + 2 < NC) {
            uint32_t sb = stage_of[s_nn];
            long ko = (long)(c + 2) * 128;
#pragma unroll
            for (int q = 0; q < 4; q++) CP16(sb + aswz[q],          gAp + ko + q*16);
#pragma unroll
            for (int q = 0; q < 4; q++) CP16(sb + SB_OFF + aswz[q], gBp + ko + q*16);
            CP_COMMIT();
        }

        s_c  = (s_c  == 2) ? 0 : s_c  + 1;
        s_nn = (s_nn == 2) ? 0 : s_nn + 1;
    }

#pragma unroll
    for (int mt = 0; mt < 4; mt++) {
        int r0 = m0 + warp_m*64 + mt*16 + (lane >> 2);
        int r1 = r0 + 8;
        size_t o0 = (size_t)r0 * ldc;
        size_t o1 = (size_t)r1 * ldc;
#pragma unroll
        for (int nt = 0; nt < 4; nt++) {
            int col = n0 + warp_n*32 + nt*8 + (lane & 3)*2;
            if (col >= N) continue;
            float v0 = acc[mt][nt][0], v1 = acc[mt][nt][1];
            float v2 = acc[mt][nt][2], v3 = acc[mt][nt][3];
            if (HALF_OUT) {
                __half* C = (__half*)Cv + (long)blockIdx.z * cStride;
                *(__half2*)(C + o0 + col) = __floats2half2_rn(v0, v1);
                *(__half2*)(C + o1 + col) = __floats2half2_rn(v2, v3);
            } else {
                float* C = (float*)Cv + (long)blockIdx.z * cStride;
                if (bias)  { float b0 = bias[col], b1 = bias[col+1];
                             v0 += b0; v1 += b1; v2 += b0; v3 += b1; }
                if (resid) { const float2 q0 = *(const float2*)(resid + o0 + col);
                             const float2 q1 = *(const float2*)(resid + o1 + col);
                             v0 += q0.x; v1 += q0.y; v2 += q1.x; v3 += q1.y; }
                *(float2*)(C + o0 + col) = make_float2(v0, v1);
                *(float2*)(C + o1 + col) = make_float2(v2, v3);
            }
        }
    }
}

// ================= fused up-GEMM + GLU: gGlu[m, j] = fp16(up1 + gelu(up2)) =================
__global__ void __launch_bounds__(256, 2) mma_gemm_glu(
    const __half* __restrict__ A,
    const __half* __restrict__ Bu,
    const float* __restrict__ up_b)
{
    extern __shared__ __align__(1024) char smem[];
    uint32_t base = smem_u32(smem);

    int tid  = threadIdx.x;
    int lane = tid & 31;
    int wid  = tid >> 5;
    int j0 = blockIdx.x * 64;
    int m0 = blockIdx.y * BM;

    int lrA = tid >> 1;
    int gA0 = (tid & 1) * 4;
    const char* pA = (const char*)(A + (long)(m0 + lrA) * KP1) + gA0*16;
    uint32_t aswz[4];
#pragma unroll
    for (int q = 0; q < 4; q++)
        aswz[q] = (uint32_t)((lrA*8 + ((gA0 + q) ^ (lrA & 7))) * 16);

    int lrB = tid >> 2;
    int gB0 = tid & 3;
    const char* pB1 = (const char*)(Bu + (long)(j0 + lrB) * KP1) + gB0*16;
    const char* pB2 = (const char*)(Bu + (long)(j0 + lrB + PROJ) * KP1) + gB0*16;
    uint32_t bswz[2];
    bswz[0] = (uint32_t)((lrB*8 + ((gB0    ) ^ (lrB & 7))) * 16);
    bswz[1] = (uint32_t)((lrB*8 + ((gB0 + 4) ^ (lrB & 7))) * 16);

    int warp_m = wid & 1;
    int warp_n = wid >> 1;

    int rAq[4];
#pragma unroll
    for (int mt = 0; mt < 4; mt++) rAq[mt] = warp_m*64 + mt*16 + (lane & 15);
    int cAoff = lane >> 4;
    int rB = warp_n*16 + ((lane >> 4) << 3) + (lane & 7);
    int cBoff = (lane >> 3) & 1;

    float acc[2][4][2][4];
#pragma unroll
    for (int h = 0; h < 2; h++)
#pragma unroll
        for (int mt = 0; mt < 4; mt++)
#pragma unroll
            for (int nt = 0; nt < 2; nt++)
#pragma unroll
                for (int q = 0; q < 4; q++) acc[h][mt][nt][q] = 0.f;

    const uint32_t B1_OFF = 16384u, B2_OFF = 24576u;
    const uint32_t STG = 32768u;
    int NC = KP1 / BK;

#pragma unroll
    for (int s = 0; s < 2; s++) {
        uint32_t sb = base + s * STG;
        long ko = (long)s * 128;
#pragma unroll
        for (int q = 0; q < 4; q++) CP16(sb + aswz[q], pA + ko + q*16);
        CP16(sb + B1_OFF + bswz[0], pB1 + ko);
        CP16(sb + B1_OFF + bswz[1], pB1 + ko + 64);
        CP16(sb + B2_OFF + bswz[0], pB2 + ko);
        CP16(sb + B2_OFF + bswz[1], pB2 + ko + 64);
        CP_COMMIT();
    }

    uint32_t stage_of[3] = { base, base + STG, base + 2*STG };
    int s_c = 0, s_nn = 2;

    for (int c = 0; c < NC; c++) {
        if (c + 1 < NC) asm volatile("cp.async.wait_group 1;" ::: "memory");
        else            asm volatile("cp.async.wait_group 0;" ::: "memory");
        __syncthreads();

        uint32_t sA = stage_of[s_c];

#pragma unroll
        for (int kk = 0; kk < 4; kk++) {
            uint32_t a[4][4], b1[2][2], b2[2][2];
            int cA = kk*2 + cAoff;
#pragma unroll
            for (int mt = 0; mt < 4; mt++) {
                int r = rAq[mt];
                uint32_t ad = sA + (uint32_t)((r*8 + (cA ^ (r & 7))) * 16);
                LDSM_X4(a[mt][0], a[mt][1], a[mt][2], a[mt][3], ad);
            }
            int cB = kk*2 + cBoff;
            uint32_t boff = (uint32_t)((rB*8 + (cB ^ (rB & 7))) * 16);
            LDSM_X4(b1[0][0], b1[0][1], b1[1][0], b1[1][1], sA + B1_OFF + boff);
            LDSM_X4(b2[0][0], b2[0][1], b2[1][0], b2[1][1], sA + B2_OFF + boff);
#pragma unroll
            for (int mt = 0; mt < 4; mt++)
#pragma unroll
                for (int nt = 0; nt < 2; nt++) {
                    MMA16816(acc[0][mt][nt], a[mt][0], a[mt][1], a[mt][2], a[mt][3],
                             b1[nt][0], b1[nt][1]);
                    MMA16816(acc[1][mt][nt], a[mt][0], a[mt][1], a[mt][2], a[mt][3],
                             b2[nt][0], b2[nt][1]);
                }
        }

        if (c + 2 < NC) {
            uint32_t sb = stage_of[s_nn];
            long ko = (long)(c + 2) * 128;
#pragma unroll
            for (int q = 0; q < 4; q++) CP16(sb + aswz[q], pA + ko + q*16);
            CP16(sb + B1_OFF + bswz[0], pB1 + ko);
            CP16(sb + B1_OFF + bswz[1], pB1 + ko + 64);
            CP16(sb + B2_OFF + bswz[0], pB2 + ko);
            CP16(sb + B2_OFF + bswz[1], pB2 + ko + 64);
            CP_COMMIT();
        }

        s_c  = (s_c  == 2) ? 0 : s_c  + 1;
        s_nn = (s_nn == 2) ? 0 : s_nn + 1;
    }

#pragma unroll
    for (int mt = 0; mt < 4; mt++) {
        int r0 = m0 + warp_m*64 + mt*16 + (lane >> 2);
        int r1 = r0 + 8;
#pragma unroll
        for (int nt = 0; nt < 2; nt++) {
            int col = j0 + warp_n*16 + nt*8 + (lane & 3)*2;
            float o0 = 0.f, o1 = 0.f, o2 = 0.f, o3 = 0.f;
            if (col < PROJ) {
                float b1v = up_b[col], b1w = up_b[col+1];
                float b2v = up_b[col + PROJ], b2w = up_b[col+1 + PROJ];
                o0 = acc[0][mt][nt][0] + b1v + gelu_t(acc[1][mt][nt][0] + b2v);
                o1 = acc[0][mt][nt][1] + b1w + gelu_t(acc[1][mt][nt][1] + b2w);
                o2 = acc[0][mt][nt][2] + b1v + gelu_t(acc[1][mt][nt][2] + b2v);
                o3 = acc[0][mt][nt][3] + b1w + gelu_t(acc[1][mt][nt][3] + b2w);
            }
            *(__half2*)(gGlu + (size_t)r0 * KP2 + col) = __floats2half2_rn(o0, o1);
            *(__half2*)(gGlu + (size_t)r1 * KP2 + col) = __floats2half2_rn(o2, o3);
        }
    }
}

// ================= weight conversion: W[K,N] -> Bt[Npad, Kpad], vectorized =================
// Tile 64k x 32n, block (32,8). Writes __half2 (128B/warp coalesced).
__device__ __forceinline__ void convW_body(const float* W, int K, int N, int Kpad, int Npad,
                                           long ldd, __half* dst)
{
    __shared__ float t[64][33];
    int k0 = blockIdx.x * 64, nn0 = blockIdx.y * 32;
    int tx = threadIdx.x, ty = threadIdx.y;   // (32, 8)
#pragma unroll
    for (int i = ty; i < 64; i += 8) {
        int k = k0 + i, n = nn0 + tx;
        t[i][tx] = (k < K && n < N) ? W[(long)k * N + n] : 0.f;
    }
    __syncthreads();
#pragma unroll
    for (int i = ty; i < 32; i += 8) {
        int n = nn0 + i;
        if (n >= Npad) continue;
        int kq = tx * 2;
        __half2 v = __floats2half2_rn(t[kq][i], t[kq+1][i]);
        *(__half2*)(dst + (long)n * ldd + k0 + kq) = v;
    }
}

__global__ void convW_k(const float* __restrict__ W, int K, int N, int Kpad, int Npad,
                        long ldd, __half* __restrict__ dst)
{
    convW_body(W, K, N, Kpad, Npad, ldd, dst);
}

__global__ void convWg2_k(const float* __restrict__ W0, const float* __restrict__ W1,
                          __half* __restrict__ dst)
{
    const float* W = (blockIdx.z == 0) ? W0 : W1;
    convW_body(W, DD, DD, KP1, DD, KP1, dst + (size_t)blockIdx.z * DD * KP1);
}

// ================= LayerNorm (eps = 2048), writes fp16 gA =================
__global__ void ln_kernel(const float* __restrict__ seq,
                          const float* __restrict__ sc,
                          const float* __restrict__ bi)
{
    int b = blockIdx.x, t = threadIdx.x;
    const float* row = seq + ((size_t)b << 11);
    float v[8]; float s = 0.f, sq = 0.f;
#pragma unroll
    for (int q = 0; q < 8; q++) { v[q] = row[q*256 + t]; s += v[q]; sq = fmaf(v[q], v[q], sq); }
    __shared__ float sh_s[8], sh_q[8];
    __shared__ float s_mu, s_inv;
#pragma unroll
    for (int o = 16; o; o >>= 1) {
        s  += __shfl_down_sync(0xffffffffu, s,  o);
        sq += __shfl_down_sync(0xffffffffu, sq, o);
    }
    int warp = t >> 5, lane = t & 31;
    if (lane == 0) { sh_s[warp] = s; sh_q[warp] = sq; }
    __syncthreads();
    if (t == 0) {
        float ts = 0.f, tq = 0.f;
        for (int w = 0; w < 8; w++) { ts += sh_s[w]; tq += sh_q[w]; }
        float mu = ts / 2048.f;
        float var = tq / 2048.f - mu*mu;
        s_mu = mu; s_inv = rsqrtf(var + 2048.0f);
    }
    __syncthreads();
    float mu = s_mu, inv = s_inv;
    __half* arow = gA + (size_t)b * KP1;
#pragma unroll
    for (int q = 0; q < 8; q++) {
        int col = q*256 + t;
        float x = (v[q] - mu) * inv * sc[col] + bi[col];
        arow[col] = __float2half(x);
    }
}

// ================= fused gating + recurrence + states + GroupNorm -> fp16 gA =================
__global__ void gate_gn_kernel(
    const float* __restrict__ b_i, const float* __restrict__ b_f,
    const float* __restrict__ b_z, const float* __restrict__ b_o,
    const float* __restrict__ Riw, const float* __restrict__ Rib,
    const float* __restrict__ Rfw, const float* __restrict__ Rfb,
    const float* __restrict__ Rzw, const float* __restrict__ Rzb,
    const float* __restrict__ Row_, const float* __restrict__ Rob,
    const float* __restrict__ c_tm1, const float* __restrict__ n_tm1,
    const float* __restrict__ h_tm1, const float* __restrict__ m_tm1,
    const float* __restrict__ gn_sc, const float* __restrict__ gn_bi,
    float* __restrict__ out, int write_states)
{
    int b = blockIdx.x, t = threadIdx.x;
    __shared__ float hrow[2048];
    __shared__ float htrow[2048];
    __shared__ float ps[256], pq[256];
    __shared__ float gmu[16], gis[16];

    size_t boff = (size_t)b << 11;
#pragma unroll
    for (int q = 0; q < 8; q++) hrow[q*256 + t] = h_tm1[boff + q*256 + t];
    __syncthreads();

    float htv[8];
#pragma unroll
    for (int q = 0; q < 8; q++) {
        int j = q*256 + t;
        size_t idx = boff + j;
        int rem = j & 127;
        int n = rem >> 3;
        int e = rem & 7;
        int jb = j & ~7;
        int sb = n*8 + e;
        int wb = n*64 + e;
        float bi_ = Rib[sb], bf_ = Rfb[sb], bz_ = Rzb[sb], bo_ = Rob[sb];
#pragma unroll
        for (int d = 0; d < 8; d++) {
            float hd = hrow[jb + d];
            bi_ = fmaf(hd, Riw[wb + d*8], bi_);
            bf_ = fmaf(hd, Rfw[wb + d*8], bf_);
            bz_ = fmaf(hd, Rzw[wb + d*8], bz_);
            bo_ = fmaf(hd, Row_[wb + d*8], bo_);
        }
        float it = __half2float(g_gates[idx])                   + b_i[j] + bi_;
        float ft = __half2float(g_gates[(size_t)N_ELE   + idx]) + b_f[j] + bf_;
        float zt = __half2float(g_gates[(size_t)2*N_ELE + idx]) + b_z[j] + bz_;
        float ot = __half2float(g_gates[(size_t)3*N_ELE + idx]) + b_o[j] + bo_;

        float mprev = m_tm1[idx];
        float mt = fmaxf(ft + mprev, it);
        float ie = expf(it - mt);
        float fe = expf(ft - mt + mprev);
        float z  = tanhf(zt);
        float ct = fe * c_tm1[idx] + ie * z;
        float nt = fe * n_tm1[idx] + ie;
        float o  = 1.f / (1.f + expf(-ot));
        float ht = o * (ct / nt);
        htv[q] = ht;
        if (write_states) {
            out[(size_t)N_ELE   + idx] = ct;
            out[(size_t)2*N_ELE + idx] = nt;
            out[(size_t)3*N_ELE + idx] = ht;
            out[(size_t)4*N_ELE + idx] = mt;
        }
    }
#pragma unroll
    for (int q = 0; q < 8; q++) htrow[q*256 + t] = htv[q];
    __syncthreads();

    int g = t >> 4, p = t & 15;
    float s = 0.f, sq = 0.f;
#pragma unroll
    for (int dg = 0; dg < 8; dg++) {
        float v = htrow[p*128 + g*8 + dg];
        s += v; sq = fmaf(v, v, sq);
    }
    ps[t] = s; pq[t] = sq;
    __syncthreads();
    for (int st = 8; st > 0; st >>= 1) {
        if (p < st) { ps[t] += ps[t + st]; pq[t] += pq[t + st]; }
        __syncthreads();
    }
    if (p == 0) {
        float mu = ps[t] / 128.f;
        float var = pq[t] / 128.f - mu*mu;
        gmu[g] = mu; gis[g] = rsqrtf(var + 1e-6f);
    }
    __syncthreads();
    __half* arow = gA + (size_t)b * KP1;
#pragma unroll
    for (int q = 0; q < 8; q++) {
        int col = q*256 + t;
        int hd = col & 127;
        int gg = hd >> 3;
        float v = (htrow[col] - gmu[gg]) * gis[gg] * gn_sc[hd] + gn_bi[hd];
        arow[col] = __float2half(v);
    }
}

// ================= driver =================
extern "C" void kernel_launch(void* const* d_in, const int* in_sizes, int n_in,
                              void* d_out, int out_size)
{
    const float* seq      = (const float*)d_in[0];
    const float* c_tm1    = (const float*)d_in[1];
    const float* n_tm1    = (const float*)d_in[2];
    const float* h_tm1    = (const float*)d_in[3];
    const float* m_tm1    = (const float*)d_in[4];
    const float* ln_scale = (const float*)d_in[5];
    const float* ln_bias  = (const float*)d_in[6];
    const float* W_z      = (const float*)d_in[7];
    const float* b_z      = (const float*)d_in[8];
    const float* W_i      = (const float*)d_in[9];
    const float* b_i      = (const float*)d_in[10];
    const float* W_f      = (const float*)d_in[11];
    const float* b_f      = (const float*)d_in[12];
    const float* W_o      = (const float*)d_in[13];
    const float* b_o      = (const float*)d_in[14];
    const float* R_z_w    = (const float*)d_in[15];
    const float* R_z_b    = (const float*)d_in[16];
    const float* R_i_w    = (const float*)d_in[17];
    const float* R_i_b    = (const float*)d_in[18];
    const float* R_f_w    = (const float*)d_in[19];
    const float* R_f_b    = (const float*)d_in[20];
    const float* R_o_w    = (const float*)d_in[21];
    const float* R_o_b    = (const float*)d_in[22];
    const float* gn_scale = (const float*)d_in[23];
    const float* gn_bias  = (const float*)d_in[24];
    const float* up_w     = (const float*)d_in[25];
    const float* up_b     = (const float*)d_in[26];
    const float* down_w   = (const float*)d_in[27];
    const float* down_b   = (const float*)d_in[28];
    float* out = (float*)d_out;

    int write_states = (out_size >= 5 * N_ELE) ? 1 : 0;

    cudaFuncSetAttribute(mma_gemm<true>,  cudaFuncAttributeMaxDynamicSharedMemorySize, SMEMSZ);
    cudaFuncSetAttribute(mma_gemm<false>, cudaFuncAttributeMaxDynamicSharedMemorySize, SMEMSZ);
    cudaFuncSetAttribute(mma_gemm_glu,    cudaFuncAttributeMaxDynamicSharedMemorySize, SMEMSZ);

    void *pA, *pGlu, *pBg, *pBu, *pBd, *pG;
    cudaGetSymbolAddress(&pA,   gA);
    cudaGetSymbolAddress(&pGlu, gGlu);
    cudaGetSymbolAddress(&pBg,  gBg);
    cudaGetSymbolAddress(&pBu,  gBu);
    cudaGetSymbolAddress(&pBd,  gBd);
    cudaGetSymbolAddress(&pG,   g_gates);
    __half* A    = (__half*)pA;
    __half* Glu  = (__half*)pGlu;
    __half* Bg   = (__half*)pBg;
    __half* Bu   = (__half*)pBu;
    __half* Bd   = (__half*)pBd;
    __half* gates = (__half*)pG;

    dim3 cw(32, 8);

    // launches #1-#5 (ncu -s 5 -c 1 profiles the gate GEMM at #6)
    ln_kernel<<<BQ, 256>>>(seq, ln_scale, ln_bias);                                   // 1
    convWg2_k<<<dim3(KP1/64, DD/32, 2), cw>>>(W_i, W_f, Bg);                          // 2
    convWg2_k<<<dim3(KP1/64, DD/32, 2), cw>>>(W_z, W_o, Bg + 2L*DD*KP1);              // 3
    convW_k<<<dim3(KP1/64, NPAD_UP/32), cw>>>(up_w, DD, UPN, KP1, NPAD_UP, KP1, Bu);  // 4
    convW_k<<<dim3(KP2/64, DD/32), cw>>>(down_w, PROJ, DD, KP2, DD, KP2, Bd);         // 5

    // 6: four gate GEMMs (batched over z), fp16 output
    mma_gemm<true><<<dim3(DD/BN, BQ/BM, 4), 256, SMEMSZ>>>(
        A, KP1, Bg, KP1, gates, DD, DD, KP1,
        (long)DD*KP1, (long)N_ELE, nullptr, nullptr);

    // 7: fused gating + recurrence + states + GroupNorm -> fp16 gA
    gate_gn_kernel<<<BQ, 256>>>(b_i, b_f, b_z, b_o,
                                R_i_w, R_i_b, R_f_w, R_f_b,
                                R_z_w, R_z_b, R_o_w, R_o_b,
                                c_tm1, n_tm1, h_tm1, m_tm1,
                                gn_scale, gn_bias,
                                out, write_states);

    // 8: fused up GEMM + GLU -> fp16 gGlu
    mma_gemm_glu<<<dim3(KP2/64, BQ/BM), 256, SMEMSZ>>>(A, Bu, up_b);

    // 9: down GEMM (+bias +residual), fp32 out
    mma_gemm<false><<<dim3(DD/BN, BQ/BM, 1), 256, SMEMSZ>>>(
        Glu, KP2, Bd, KP2, out, DD, DD, KP2, 0, 0, down_b, seq);
}